// round 10
// baseline (speedup 1.0000x reference)
#include <cuda_runtime.h>
#include <cuda_fp16.h>
#include <cstdint>
#include <math.h>

// ---------------- problem constants ----------------
#define Bc 1024   // batch
#define Tc 40     // timesteps
#define Ec 512    // embed dim
#define Hc 1024   // hidden
#define Lc 256    // latent out
#define Ac 2048   // feature dim
#define Vc 30000  // vocab
#define Nw 4096   // 4*H

// ---------------- device scratch (no allocation) ----------------
__device__ __half g_Wcat [2 * Hc * Ac];
__device__ float  g_bcat [2 * Hc];
__device__ __half g_Wocat[2 * Lc * Hc];
__device__ float  g_bocat[2 * Lc];
__device__ __half g_Wp   [Nw * (Hc + Ec)];
__device__ float  g_pb   [Nw];
__device__ __half g_hbuf [2][Bc * Hc];
__device__ float  g_c0   [Bc * Hc];
__device__ __half g_hl   [Bc * Hc];
__device__ __half g_embH [Vc * Ec];
__device__ __half g_ftH  [Bc * Ac];
__device__ unsigned int g_flags[256];     // [bm_group 8][producer 32] step counters

// ---------------- helpers ----------------
__device__ __forceinline__ uint32_t smem_u32(const void* p) {
    uint32_t a;
    asm("{ .reg .u64 t; cvta.to.shared.u64 t, %1; cvt.u32.u64 %0, t; }" : "=r"(a) : "l"(p));
    return a;
}
#define CP_ASYNC16(dst, src) \
    asm volatile("cp.async.cg.shared.global [%0], [%1], 16;" :: "r"(dst), "l"(src))
#define CP_COMMIT() asm volatile("cp.async.commit_group;" ::: "memory")
#define CP_WAIT2()  asm volatile("cp.async.wait_group 2;" ::: "memory")

__device__ __forceinline__ void mma_f16(float* d, const uint32_t* a, const uint32_t* b) {
    asm volatile(
        "mma.sync.aligned.m16n8k16.row.col.f32.f16.f16.f32 "
        "{%0,%1,%2,%3}, {%4,%5,%6,%7}, {%8,%9}, {%0,%1,%2,%3};"
        : "+f"(d[0]), "+f"(d[1]), "+f"(d[2]), "+f"(d[3])
        : "r"(a[0]), "r"(a[1]), "r"(a[2]), "r"(a[3]), "r"(b[0]), "r"(b[1]));
}
__device__ __forceinline__ void ldsm_x4(uint32_t* r, uint32_t addr) {
    asm volatile("ldmatrix.sync.aligned.m8n8.x4.shared.b16 {%0,%1,%2,%3}, [%4];"
        : "=r"(r[0]), "=r"(r[1]), "=r"(r[2]), "=r"(r[3]) : "r"(addr));
}
__device__ __forceinline__ float fex2(float x) { float r; asm("ex2.approx.f32 %0, %1;" : "=f"(r) : "f"(x)); return r; }
__device__ __forceinline__ float frcp(float x) { float r; asm("rcp.approx.f32 %0, %1;" : "=f"(r) : "f"(x)); return r; }
__device__ __forceinline__ float fsig(float x)  { return frcp(1.f + fex2(-1.4426950408889634f * x)); }
__device__ __forceinline__ float ftanh(float x) { return 1.f - 2.f * frcp(1.f + fex2(2.8853900817779268f * x)); }

// ---------------- prep kernels ----------------
__global__ void wn_kernel(const float* __restrict__ v, const float* __restrict__ g,
                          __half* __restrict__ W, int cols) {
    int r = blockIdx.x;
    const float* vr = v + (size_t)r * cols;
    float s = 0.f;
    for (int c = threadIdx.x; c < cols; c += blockDim.x) { float x = vr[c]; s += x * x; }
    __shared__ float sh[32];
    for (int o = 16; o > 0; o >>= 1) s += __shfl_down_sync(0xffffffffu, s, o);
    if ((threadIdx.x & 31) == 0) sh[threadIdx.x >> 5] = s;
    __syncthreads();
    if (threadIdx.x < 32) {
        float t = (threadIdx.x < (blockDim.x >> 5)) ? sh[threadIdx.x] : 0.f;
        for (int o = 16; o > 0; o >>= 1) t += __shfl_down_sync(0xffffffffu, t, o);
        if (threadIdx.x == 0) sh[0] = t;
    }
    __syncthreads();
    float scale = g[r] / sqrtf(sh[0]);
    __half* Wr = W + (size_t)r * cols;
    for (int c = threadIdx.x; c < cols; c += blockDim.x) Wr[c] = __float2half_rn(vr[c] * scale);
}

__global__ void permute_kernel(const float* __restrict__ Whh, const float* __restrict__ Wih,
                               const float* __restrict__ bih, const float* __restrict__ bhh,
                               __half* __restrict__ Wp, float* __restrict__ pb) {
    int n = blockIdx.x;
    int gt = n >> 10, j = n & 1023;
    int np = (j << 2) | gt;
    __half* dst = Wp + (size_t)np * (Hc + Ec);
    const float* s1 = Whh + (size_t)n * Hc;
    const float* s2 = Wih + (size_t)n * Ec;
    for (int k = threadIdx.x; k < Hc; k += blockDim.x) dst[k] = __float2half_rn(s1[k]);
    for (int k = threadIdx.x; k < Ec; k += blockDim.x) dst[Hc + k] = __float2half_rn(s2[k]);
    if (threadIdx.x == 0) pb[np] = bih[n] + bhh[n];
}

__global__ void half_copy(const float* __restrict__ src, __half* __restrict__ dst, int n) {
    int i = blockIdx.x * blockDim.x + threadIdx.x;
    if (i < n) dst[i] = __float2half_rn(src[i]);
}

__global__ void pack2(const float* __restrict__ a, const float* __restrict__ b,
                      float* __restrict__ dst, int n) {
    int i = blockIdx.x * blockDim.x + threadIdx.x;
    if (i < n) dst[i] = a[i];
    else if (i < 2 * n) dst[i] = b[i - n];
}

// ---------------- fp16 mma.sync GEMM (init / output projections) ----------------
static constexpr int ST    = 128 * 80;                    // 10240 B per stage
static constexpr int A_OFF = 1024;
static constexpr int B_OFF = A_OFF + 4 * ST;
static constexpr int SMEM_G = B_OFF + 4 * ST;             // 82944

__global__ __launch_bounds__(256, 2)
void hgemm(const __half* __restrict__ A1, int lda1, int kc1,
           const __half* __restrict__ Bw, int ldb,
           const float* __restrict__ bias,
           float* __restrict__ C1, int ldc1, int half1,
           float* __restrict__ C2, int ldc2, int half2, int ncut)
{
    extern __shared__ __align__(1024) char smem[];
    uint32_t sb = smem_u32(smem);
    int tid = threadIdx.x, wid = tid >> 5, lid = tid & 31;
    int g = lid >> 2, tig = lid & 3;
    int warpM = (wid & 1) * 64, warpN = (wid >> 1) * 32;
    int bm = blockIdx.y * 128, bn = blockIdx.x * 128;
    const int NC = kc1;

    uint32_t offA[4], offB[2];
#pragma unroll
    for (int rb = 0; rb < 4; rb++)
        offA[rb] = (warpM + rb * 16 + (lid & 15)) * 80 + (lid >> 4) * 16;
#pragma unroll
    for (int p = 0; p < 2; p++)
        offB[p] = (warpN + p * 16 + ((lid >> 4) << 3) + (lid & 7)) * 80 + ((lid >> 3) & 1) * 16;

    float acc[4][4][4];
#pragma unroll
    for (int i = 0; i < 4; i++)
#pragma unroll
        for (int j = 0; j < 4; j++)
#pragma unroll
            for (int q = 0; q < 4; q++) acc[i][j][q] = 0.f;

    auto load_chunk = [&](int c, int s) {
        uint32_t aB = sb + A_OFF + s * ST;
        uint32_t bB = sb + B_OFF + s * ST;
#pragma unroll
        for (int i = 0; i < 2; i++) {
            int seg = tid + i * 256;
            int m = seg >> 2, sg = seg & 3;
            CP_ASYNC16(aB + m * 80 + sg * 16, A1 + (size_t)(bm + m) * lda1 + c * 32 + sg * 8);
        }
#pragma unroll
        for (int i = 0; i < 2; i++) {
            int seg = tid + i * 256;
            int n = seg >> 2, sg = seg & 3;
            CP_ASYNC16(bB + n * 80 + sg * 16, Bw + (size_t)(bn + n) * ldb + c * 32 + sg * 8);
        }
    };

    for (int p = 0; p < 3; p++) { load_chunk(p, p); CP_COMMIT(); }

    for (int c = 0; c < NC; c++) {
        int s = c & 3;
        CP_WAIT2();
        __syncthreads();
        if (c + 3 < NC) load_chunk(c + 3, (c + 3) & 3);
        CP_COMMIT();
        uint32_t aB = sb + A_OFF + s * ST;
        uint32_t bB = sb + B_OFF + s * ST;
#pragma unroll
        for (int k16 = 0; k16 < 2; k16++) {
            uint32_t afr[4][4], bfr[2][4];
#pragma unroll
            for (int rb = 0; rb < 4; rb++) ldsm_x4(afr[rb], aB + offA[rb] + k16 * 32);
#pragma unroll
            for (int p = 0; p < 2; p++) ldsm_x4(bfr[p], bB + offB[p] + k16 * 32);
#pragma unroll
            for (int rb = 0; rb < 4; rb++) {
                mma_f16(acc[rb][0], afr[rb], &bfr[0][0]);
                mma_f16(acc[rb][1], afr[rb], &bfr[0][2]);
                mma_f16(acc[rb][2], afr[rb], &bfr[1][0]);
                mma_f16(acc[rb][3], afr[rb], &bfr[1][2]);
            }
        }
    }

    float* Cd; int cb, ldc, hf;
    if (bn < ncut) { Cd = C1; cb = bn;        ldc = ldc1; hf = half1; }
    else           { Cd = C2; cb = bn - ncut; ldc = ldc2; hf = half2; }
#pragma unroll
    for (int rb = 0; rb < 4; rb++) {
#pragma unroll
        for (int nb = 0; nb < 4; nb++) {
            int coll = warpN + nb * 8 + 2 * tig;
            int col = cb + coll;
            int r0 = bm + warpM + rb * 16 + g;
            float b0 = bias[bn + coll], b1 = bias[bn + coll + 1];
            float v0 = acc[rb][nb][0] + b0, v1 = acc[rb][nb][1] + b1;
            float v2 = acc[rb][nb][2] + b0, v3 = acc[rb][nb][3] + b1;
            if (hf) {
                __half* Ch = (__half*)Cd;
                *(__half2*)(Ch + (size_t)r0 * ldc + col)       = __floats2half2_rn(v0, v1);
                *(__half2*)(Ch + (size_t)(r0 + 8) * ldc + col) = __floats2half2_rn(v2, v3);
            } else {
                *(float2*)(Cd + (size_t)r0 * ldc + col)       = make_float2(v0, v1);
                *(float2*)(Cd + (size_t)(r0 + 8) * ldc + col) = make_float2(v2, v3);
            }
        }
    }
}

// ---------------- persistent LSTM recurrence (dataflow flags, continuous pipeline) ----------------
// smem: [0,1024) stok[2][128]; 8 pipeline stages; SEPARATE h staging; c state; cap_len.
static constexpr int PA_OFF = 1024;                       // stages A(4) then B(4)
static constexpr int HS_OFF = PA_OFF + 8 * ST;            // 82944: h staging 128*34*2 = 8704
static constexpr int CS_OFF = HS_OFF + 8704;              // 91648: c 128*33*4 = 16896
static constexpr int CL_OFF = CS_OFF + 16896;             // 108544
static constexpr int SMEM_P = CL_OFF + 512;               // 109056

#define NCHUNK 48
#define TOTCH  (Tc * NCHUNK)

__global__ __launch_bounds__(256, 2)
void lstm_persist(const __half* __restrict__ embH,
                  const int* __restrict__ cap,
                  const __half* __restrict__ Wp,
                  const float* __restrict__ pb,
                  const float* __restrict__ c0,
                  __half* __restrict__ hbuf,
                  __half* __restrict__ hlast,
                  const int* __restrict__ cap_len,
                  unsigned int* __restrict__ flags)
{
    extern __shared__ __align__(1024) char smem[];
    uint32_t sb = smem_u32(smem);
    int tid = threadIdx.x, wid = tid >> 5, lid = tid & 31;
    int g = lid >> 2, tig = lid & 3;
    int warpM = (wid & 1) * 64, warpN = (wid >> 1) * 32;
    int myIdx = blockIdx.x;                 // producer id within bm-group
    int bn = myIdx * 128, bm = blockIdx.y * 128;
    int jg0 = bn >> 2;
    int* stok0 = (int*)smem;
    int* stok1 = (int*)(smem + 512);
    __half* hsm = (__half*)(smem + HS_OFF);
    float*  c_s = (float*)(smem + CS_OFF);
    int* cl_s   = (int*)(smem + CL_OFF);
    unsigned int* gflag = flags + blockIdx.y * 32;
    unsigned int* myflag = gflag + myIdx;

    uint32_t offA[4], offB[2];
#pragma unroll
    for (int rb = 0; rb < 4; rb++)
        offA[rb] = (warpM + rb * 16 + (lid & 15)) * 80 + (lid >> 4) * 16;
#pragma unroll
    for (int p = 0; p < 2; p++)
        offB[p] = (warpN + p * 16 + ((lid >> 4) << 3) + (lid & 7)) * 80 + ((lid >> 3) & 1) * 16;

    for (int idx = tid; idx < 128 * 32; idx += 256) {
        int row = idx >> 5, jl = idx & 31;
        c_s[row * 33 + jl] = c0[(size_t)(bm + row) * Hc + jg0 + jl];
    }
    if (tid < 128) {
        cl_s[tid]  = cap_len[bm + tid];
        stok0[tid] = cap[(size_t)(bm + tid) * Tc + 0];
    }
    __syncthreads();

    // load global chunk gc: step tt = gc/48; position c2 = gc%48.
    // c2 < 16: embed chunk c2 (cols Hc + c2*32 of Wp); else h chunk kc = (myIdx + c2-16) & 31.
    auto load_chunk = [&](int gc) {
        int tt = gc / NCHUNK, c2 = gc % NCHUNK;
        int s = gc & 3;
        uint32_t aB = sb + PA_OFF + s * ST;
        uint32_t bB = sb + PA_OFF + 4 * ST + s * ST;
        const int* tok = (tt & 1) ? stok1 : stok0;
        const __half* hin = hbuf + (size_t)(tt & 1) * (Bc * Hc);
        bool emb = (c2 < 16);
        int kc = emb ? c2 : ((myIdx + c2 - 16) & 31);
#pragma unroll
        for (int i = 0; i < 2; i++) {
            int seg = tid + i * 256;
            int m = seg >> 2, sg = seg & 3;
            const __half* src = emb
                ? embH + (size_t)tok[m] * Ec + kc * 32 + sg * 8
                : hin + (size_t)(bm + m) * Hc + kc * 32 + sg * 8;
            CP_ASYNC16(aB + m * 80 + sg * 16, src);
        }
        int kk = emb ? (Hc + kc * 32) : (kc * 32);
#pragma unroll
        for (int i = 0; i < 2; i++) {
            int seg = tid + i * 256;
            int n = seg >> 2, sg = seg & 3;
            CP_ASYNC16(bB + n * 80 + sg * 16,
                       Wp + (size_t)(bn + n) * (Hc + Ec) + kk + sg * 8);
        }
    };

    // prologue: first 3 chunks of t=0 (embed)
    for (int p = 0; p < 3; p++) { load_chunk(p); CP_COMMIT(); }

    for (int t = 0; t < Tc; t++) {
        float acc[4][4][4];
#pragma unroll
        for (int i = 0; i < 4; i++)
#pragma unroll
            for (int j = 0; j < 4; j++)
#pragma unroll
                for (int q = 0; q < 4; q++) acc[i][j][q] = 0.f;

        for (int c = 0; c < NCHUNK; c++) {
            int gc = t * NCHUNK + c;
            int gl = gc + 3;
            // dataflow wait: chunk gl is an h-chunk -> need its producer done with step t-? :
            // h-chunks of step t need producer finished step t-1, i.e. flag >= t.
            if (gl < TOTCH) {
                int c3 = gl % NCHUNK;
                if (c3 >= 16 && tid == 0) {
                    int p = (myIdx + c3 - 16) & 31;
                    unsigned int v;
                    do {
                        asm volatile("ld.acquire.gpu.global.u32 %0, [%1];"
                                     : "=r"(v) : "l"(gflag + p) : "memory");
                    } while (v < (unsigned int)t);
                }
            }
            if (c == 44 && t + 1 < Tc && tid < 128) {
                int* tok_next = ((t + 1) & 1) ? stok1 : stok0;
                tok_next[tid] = cap[(size_t)(bm + tid) * Tc + t + 1];
            }
            int s = gc & 3;
            CP_WAIT2();
            __syncthreads();            // data ready + stage (gl&3) free + tok/poll visible
            if (gl < TOTCH) load_chunk(gl);
            CP_COMMIT();
            uint32_t aB = sb + PA_OFF + s * ST;
            uint32_t bB = sb + PA_OFF + 4 * ST + s * ST;
#pragma unroll
            for (int k16 = 0; k16 < 2; k16++) {
                uint32_t afr[4][4], bfr[2][4];
#pragma unroll
                for (int rb = 0; rb < 4; rb++) ldsm_x4(afr[rb], aB + offA[rb] + k16 * 32);
#pragma unroll
                for (int p = 0; p < 2; p++) ldsm_x4(bfr[p], bB + offB[p] + k16 * 32);
#pragma unroll
                for (int rb = 0; rb < 4; rb++) {
                    mma_f16(acc[rb][0], afr[rb], &bfr[0][0]);
                    mma_f16(acc[rb][1], afr[rb], &bfr[0][2]);
                    mma_f16(acc[rb][2], afr[rb], &bfr[1][0]);
                    mma_f16(acc[rb][3], afr[rb], &bfr[1][2]);
                }
            }
        }

        // shuffle epilogue: gates in registers, c in smem, stage only h (separate buffer)
        __half* hout = hbuf + (size_t)((t + 1) & 1) * (Bc * Hc);
#pragma unroll
        for (int rb = 0; rb < 4; rb++) {
#pragma unroll
            for (int nb = 0; nb < 4; nb++) {
                int r0 = warpM + rb * 16 + g;
                float v0 = acc[rb][nb][0], v1 = acc[rb][nb][1];
                float v2 = acc[rb][nb][2], v3 = acc[rb][nb][3];
                bool ev = (tig & 1) == 0;
                float x = ev ? v2 : v0, y = ev ? v3 : v1;
                float px = __shfl_xor_sync(0xffffffffu, x, 1);
                float py = __shfl_xor_sync(0xffffffffu, y, 1);
                float gi = ev ? v0 : px, gf = ev ? v1 : py;
                float gg = ev ? px : v2, go = ev ? py : v3;
                int rrow = ev ? r0 : (r0 + 8);
                int Jl = (warpN >> 2) + 2 * nb + (tig >> 1);
                float4 pbv = *(const float4*)(pb + 4 * (jg0 + Jl));
                float si = fsig(gi + pbv.x);
                float sf = fsig(gf + pbv.y);
                float tg = ftanh(gg + pbv.z);
                float so = fsig(go + pbv.w);
                int ci = rrow * 33 + Jl;
                float cn = sf * c_s[ci] + si * tg;
                c_s[ci] = cn;
                hsm[rrow * 34 + Jl] = __float2half_rn(so * ftanh(cn));
            }
        }
        __syncthreads();
        for (int idx = tid; idx < 128 * 32; idx += 256) {
            int row = idx >> 5, jl = idx & 31;
            __half hv = hsm[row * 34 + jl];
            size_t off = (size_t)(bm + row) * Hc + jg0 + jl;
            hout[off] = hv;
            if (cl_s[row] - 1 == t) hlast[off] = hv;
        }
        __syncthreads();                // all h stores issued before release
        if (tid == 0)
            asm volatile("red.release.gpu.global.add.u32 [%0], %1;"
                         :: "l"(myflag), "r"(1u) : "memory");
    }
}

// ---------------- launch ----------------
extern "C" void kernel_launch(void* const* d_in, const int* in_sizes, int n_in,
                              void* d_out, int out_size) {
    const int*   cap     = (const int*)  d_in[0];
    const int*   cap_len = (const int*)  d_in[1];
    const float* feat    = (const float*)d_in[2];
    const float* embed   = (const float*)d_in[3];
    const float* W_ih    = (const float*)d_in[4];
    const float* W_hh    = (const float*)d_in[5];
    const float* b_ih    = (const float*)d_in[6];
    const float* b_hh    = (const float*)d_in[7];
    const float* v_ih0   = (const float*)d_in[8];
    const float* g_ih0   = (const float*)d_in[9];
    const float* b_ih0   = (const float*)d_in[10];
    const float* v_ic0   = (const float*)d_in[11];
    const float* g_ic0   = (const float*)d_in[12];
    const float* b_ic0   = (const float*)d_in[13];
    const float* v_mu    = (const float*)d_in[14];
    const float* g_mu    = (const float*)d_in[15];
    const float* b_mu    = (const float*)d_in[16];
    const float* v_s2    = (const float*)d_in[17];
    const float* g_s2    = (const float*)d_in[18];
    const float* b_s2    = (const float*)d_in[19];
    float* out = (float*)d_out;

    __half *Wcat, *Wocat, *Wp, *hbuf, *hl, *embH, *ftH;
    float *bcat, *bocat, *pb, *c0;
    unsigned int* flags;
    cudaGetSymbolAddress((void**)&Wcat,  g_Wcat);
    cudaGetSymbolAddress((void**)&bcat,  g_bcat);
    cudaGetSymbolAddress((void**)&Wocat, g_Wocat);
    cudaGetSymbolAddress((void**)&bocat, g_bocat);
    cudaGetSymbolAddress((void**)&Wp,    g_Wp);
    cudaGetSymbolAddress((void**)&pb,    g_pb);
    cudaGetSymbolAddress((void**)&hbuf,  g_hbuf);
    cudaGetSymbolAddress((void**)&c0,    g_c0);
    cudaGetSymbolAddress((void**)&hl,    g_hl);
    cudaGetSymbolAddress((void**)&embH,  g_embH);
    cudaGetSymbolAddress((void**)&ftH,   g_ftH);
    cudaGetSymbolAddress((void**)&flags, g_flags);

    cudaFuncSetAttribute(hgemm,        cudaFuncAttributeMaxDynamicSharedMemorySize, SMEM_G);
    cudaFuncSetAttribute(lstm_persist, cudaFuncAttributeMaxDynamicSharedMemorySize, SMEM_P);

    cudaMemsetAsync(flags, 0, 256 * sizeof(unsigned int));

    wn_kernel<<<Hc, 256>>>(v_ih0, g_ih0, Wcat,            Ac);
    wn_kernel<<<Hc, 256>>>(v_ic0, g_ic0, Wcat + Hc * Ac,  Ac);
    wn_kernel<<<Lc, 256>>>(v_mu,  g_mu,  Wocat,           Hc);
    wn_kernel<<<Lc, 256>>>(v_s2,  g_s2,  Wocat + Lc * Hc, Hc);
    pack2<<<(2 * Hc + 255) / 256, 256>>>(b_ih0, b_ic0, bcat, Hc);
    pack2<<<(2 * Lc + 255) / 256, 256>>>(b_mu,  b_s2,  bocat, Lc);
    permute_kernel<<<Nw, 256>>>(W_hh, W_ih, b_ih, b_hh, Wp, pb);
    half_copy<<<(Vc * Ec + 255) / 256, 256>>>(embed, embH, Vc * Ec);
    half_copy<<<(Bc * Ac + 255) / 256, 256>>>(feat, ftH, Bc * Ac);

    // init: h0 (fp16, into hbuf[0]) and c0 (fp32), fused N=2048
    {
        dim3 grid(2 * Hc / 128, Bc / 128);   // (16, 8)
        hgemm<<<grid, 256, SMEM_G>>>(ftH, Ac, Ac / 32, Wcat, Ac, bcat,
                                     (float*)hbuf, Hc, 1, c0, Hc, 0, Hc);
    }

    // recurrence: ONE persistent kernel, per-producer dataflow flags
    {
        dim3 grid(Nw / 128, Bc / 128);       // (32, 8) = 256 CTAs, 2/SM all resident
        lstm_persist<<<grid, 256, SMEM_P>>>(embH, cap, Wp, pb, c0, hbuf, hl, cap_len, flags);
    }

    // outputs: mu and sigma2 fused, N=512
    {
        dim3 grid(2 * Lc / 128, Bc / 128);   // (4, 8)
        hgemm<<<grid, 256, SMEM_G>>>(hl, Hc, Hc / 32, Wocat, Hc, bocat,
                                     out, Lc, 0, out + Bc * Lc, Lc, 0, Lc);
    }
}

// round 13
// speedup vs baseline: 1.2201x; 1.2201x over previous
#include <cuda_runtime.h>
#include <cuda_fp16.h>
#include <cstdint>
#include <math.h>

// ---------------- problem constants ----------------
#define Bc 1024   // batch
#define Tc 40     // timesteps
#define Ec 512    // embed dim
#define Hc 1024   // hidden
#define Lc 256    // latent out
#define Ac 2048   // feature dim
#define Vc 30000  // vocab
#define Nw 4096   // 4*H
#define NCTA 256

// ---------------- device scratch (no allocation) ----------------
__device__ __half g_Wcat [2 * Hc * Ac];
__device__ float  g_bcat [2 * Hc];
__device__ __half g_Wocat[2 * Lc * Hc];
__device__ float  g_bocat[2 * Lc];
__device__ __half g_Wp   [Nw * (Hc + Ec)];
__device__ float  g_pb   [Nw];
__device__ __half g_hbuf [2][Bc * Hc];
__device__ float  g_c0   [Bc * Hc];
__device__ __half g_hl   [Bc * Hc];
__device__ __half g_embH [Vc * Ec];
__device__ __half g_ftH  [Bc * Ac];
__device__ unsigned int g_counter;

// ---------------- helpers ----------------
__device__ __forceinline__ uint32_t smem_u32(const void* p) {
    uint32_t a;
    asm("{ .reg .u64 t; cvta.to.shared.u64 t, %1; cvt.u32.u64 %0, t; }" : "=r"(a) : "l"(p));
    return a;
}
#define CP_ASYNC16(dst, src) \
    asm volatile("cp.async.cg.shared.global [%0], [%1], 16;" :: "r"(dst), "l"(src))
#define CP_COMMIT() asm volatile("cp.async.commit_group;" ::: "memory")
#define CP_WAIT2()  asm volatile("cp.async.wait_group 2;" ::: "memory")
#define CP_WAIT1()  asm volatile("cp.async.wait_group 1;" ::: "memory")

__device__ __forceinline__ void mma_f16(float* d, const uint32_t* a, const uint32_t* b) {
    asm volatile(
        "mma.sync.aligned.m16n8k16.row.col.f32.f16.f16.f32 "
        "{%0,%1,%2,%3}, {%4,%5,%6,%7}, {%8,%9}, {%0,%1,%2,%3};"
        : "+f"(d[0]), "+f"(d[1]), "+f"(d[2]), "+f"(d[3])
        : "r"(a[0]), "r"(a[1]), "r"(a[2]), "r"(a[3]), "r"(b[0]), "r"(b[1]));
}
__device__ __forceinline__ void ldsm_x4(uint32_t* r, uint32_t addr) {
    asm volatile("ldmatrix.sync.aligned.m8n8.x4.shared.b16 {%0,%1,%2,%3}, [%4];"
        : "=r"(r[0]), "=r"(r[1]), "=r"(r[2]), "=r"(r[3]) : "r"(addr));
}
__device__ __forceinline__ float fex2(float x) { float r; asm("ex2.approx.f32 %0, %1;" : "=f"(r) : "f"(x)); return r; }
__device__ __forceinline__ float frcp(float x) { float r; asm("rcp.approx.f32 %0, %1;" : "=f"(r) : "f"(x)); return r; }
__device__ __forceinline__ float fsig(float x)  { return frcp(1.f + fex2(-1.4426950408889634f * x)); }
__device__ __forceinline__ float ftanh(float x) { return 1.f - 2.f * frcp(1.f + fex2(2.8853900817779268f * x)); }

// ---------------- prep kernels ----------------
__global__ void wn_kernel(const float* __restrict__ v, const float* __restrict__ g,
                          __half* __restrict__ W, int cols) {
    int r = blockIdx.x;
    const float* vr = v + (size_t)r * cols;
    float s = 0.f;
    for (int c = threadIdx.x; c < cols; c += blockDim.x) { float x = vr[c]; s += x * x; }
    __shared__ float sh[32];
    for (int o = 16; o > 0; o >>= 1) s += __shfl_down_sync(0xffffffffu, s, o);
    if ((threadIdx.x & 31) == 0) sh[threadIdx.x >> 5] = s;
    __syncthreads();
    if (threadIdx.x < 32) {
        float t = (threadIdx.x < (blockDim.x >> 5)) ? sh[threadIdx.x] : 0.f;
        for (int o = 16; o > 0; o >>= 1) t += __shfl_down_sync(0xffffffffu, t, o);
        if (threadIdx.x == 0) sh[0] = t;
    }
    __syncthreads();
    float scale = g[r] / sqrtf(sh[0]);
    __half* Wr = W + (size_t)r * cols;
    for (int c = threadIdx.x; c < cols; c += blockDim.x) Wr[c] = __float2half_rn(vr[c] * scale);
}

__global__ void permute_kernel(const float* __restrict__ Whh, const float* __restrict__ Wih,
                               const float* __restrict__ bih, const float* __restrict__ bhh,
                               __half* __restrict__ Wp, float* __restrict__ pb) {
    int n = blockIdx.x;
    int gt = n >> 10, j = n & 1023;
    int np = (j << 2) | gt;
    __half* dst = Wp + (size_t)np * (Hc + Ec);
    const float* s1 = Whh + (size_t)n * Hc;
    const float* s2 = Wih + (size_t)n * Ec;
    for (int k = threadIdx.x; k < Hc; k += blockDim.x) dst[k] = __float2half_rn(s1[k]);
    for (int k = threadIdx.x; k < Ec; k += blockDim.x) dst[Hc + k] = __float2half_rn(s2[k]);
    if (threadIdx.x == 0) pb[np] = bih[n] + bhh[n];
}

__global__ void half_copy(const float* __restrict__ src, __half* __restrict__ dst, int n) {
    int i = blockIdx.x * blockDim.x + threadIdx.x;
    if (i < n) dst[i] = __float2half_rn(src[i]);
}

__global__ void pack2(const float* __restrict__ a, const float* __restrict__ b,
                      float* __restrict__ dst, int n) {
    int i = blockIdx.x * blockDim.x + threadIdx.x;
    if (i < n) dst[i] = a[i];
    else if (i < 2 * n) dst[i] = b[i - n];
}

// ---------------- fp16 mma.sync GEMM (init / output projections) — R8-proven ----------------
static constexpr int ST    = 128 * 80;
static constexpr int A_OFF = 1024;
static constexpr int B_OFF = A_OFF + 4 * ST;
static constexpr int SMEM_G = B_OFF + 4 * ST;             // 82944

__global__ __launch_bounds__(256, 2)
void hgemm(const __half* __restrict__ A1, int lda1, int kc1,
           const __half* __restrict__ Bw, int ldb,
           const float* __restrict__ bias,
           float* __restrict__ C1, int ldc1, int half1,
           float* __restrict__ C2, int ldc2, int half2, int ncut)
{
    extern __shared__ __align__(1024) char smem[];
    uint32_t sb = smem_u32(smem);
    int tid = threadIdx.x, wid = tid >> 5, lid = tid & 31;
    int g = lid >> 2, tig = lid & 3;
    int warpM = (wid & 1) * 64, warpN = (wid >> 1) * 32;
    int bm = blockIdx.y * 128, bn = blockIdx.x * 128;
    const int NC = kc1;

    uint32_t offA[4], offB[2];
#pragma unroll
    for (int rb = 0; rb < 4; rb++)
        offA[rb] = (warpM + rb * 16 + (lid & 15)) * 80 + (lid >> 4) * 16;
#pragma unroll
    for (int p = 0; p < 2; p++)
        offB[p] = (warpN + p * 16 + ((lid >> 4) << 3) + (lid & 7)) * 80 + ((lid >> 3) & 1) * 16;

    float acc[4][4][4];
#pragma unroll
    for (int i = 0; i < 4; i++)
#pragma unroll
        for (int j = 0; j < 4; j++)
#pragma unroll
            for (int q = 0; q < 4; q++) acc[i][j][q] = 0.f;

    auto load_chunk = [&](int c, int s) {
        uint32_t aB = sb + A_OFF + s * ST;
        uint32_t bB = sb + B_OFF + s * ST;
#pragma unroll
        for (int i = 0; i < 2; i++) {
            int seg = tid + i * 256;
            int m = seg >> 2, sg = seg & 3;
            CP_ASYNC16(aB + m * 80 + sg * 16, A1 + (size_t)(bm + m) * lda1 + c * 32 + sg * 8);
        }
#pragma unroll
        for (int i = 0; i < 2; i++) {
            int seg = tid + i * 256;
            int n = seg >> 2, sg = seg & 3;
            CP_ASYNC16(bB + n * 80 + sg * 16, Bw + (size_t)(bn + n) * ldb + c * 32 + sg * 8);
        }
    };

    for (int p = 0; p < 3; p++) { load_chunk(p, p); CP_COMMIT(); }

    for (int c = 0; c < NC; c++) {
        int s = c & 3;
        CP_WAIT2();
        __syncthreads();
        if (c + 3 < NC) load_chunk(c + 3, (c + 3) & 3);
        CP_COMMIT();
        uint32_t aB = sb + A_OFF + s * ST;
        uint32_t bB = sb + B_OFF + s * ST;
#pragma unroll
        for (int k16 = 0; k16 < 2; k16++) {
            uint32_t afr[4][4], bfr[2][4];
#pragma unroll
            for (int rb = 0; rb < 4; rb++) ldsm_x4(afr[rb], aB + offA[rb] + k16 * 32);
#pragma unroll
            for (int p = 0; p < 2; p++) ldsm_x4(bfr[p], bB + offB[p] + k16 * 32);
#pragma unroll
            for (int rb = 0; rb < 4; rb++) {
                mma_f16(acc[rb][0], afr[rb], &bfr[0][0]);
                mma_f16(acc[rb][1], afr[rb], &bfr[0][2]);
                mma_f16(acc[rb][2], afr[rb], &bfr[1][0]);
                mma_f16(acc[rb][3], afr[rb], &bfr[1][2]);
            }
        }
    }

    float* Cd; int cb, ldc, hf;
    if (bn < ncut) { Cd = C1; cb = bn;        ldc = ldc1; hf = half1; }
    else           { Cd = C2; cb = bn - ncut; ldc = ldc2; hf = half2; }
#pragma unroll
    for (int rb = 0; rb < 4; rb++) {
#pragma unroll
        for (int nb = 0; nb < 4; nb++) {
            int coll = warpN + nb * 8 + 2 * tig;
            int col = cb + coll;
            int r0 = bm + warpM + rb * 16 + g;
            float b0 = bias[bn + coll], b1 = bias[bn + coll + 1];
            float v0 = acc[rb][nb][0] + b0, v1 = acc[rb][nb][1] + b1;
            float v2 = acc[rb][nb][2] + b0, v3 = acc[rb][nb][3] + b1;
            if (hf) {
                __half* Ch = (__half*)Cd;
                *(__half2*)(Ch + (size_t)r0 * ldc + col)       = __floats2half2_rn(v0, v1);
                *(__half2*)(Ch + (size_t)(r0 + 8) * ldc + col) = __floats2half2_rn(v2, v3);
            } else {
                *(float2*)(Cd + (size_t)r0 * ldc + col)       = make_float2(v0, v1);
                *(float2*)(Cd + (size_t)(r0 + 8) * ldc + col) = make_float2(v2, v3);
            }
        }
    }
}

// ---------------- persistent LSTM recurrence: K=64 superchunks, c in registers ----------------
// NSC = 24: superchunks 0..7 = embed (E=512), 8..23 = hidden (H=1024).  [R12 bug: was 16]
// smem: [0,512) stok, [512,1024) pb_s, [1024,1536) cl_s, [2048, +6*18432) stages (3 A, 3 B).
// h staging (8704 B) overlays stage A0 (stage 0 last read at iter 21; free at epilogue).
static constexpr int SC_ST  = 128 * 144;                  // 18432 per stage
static constexpr int SA_OFF = 2048;
static constexpr int SB_OFF = SA_OFF + 3 * SC_ST;         // 57344
static constexpr int SMEM_P = SB_OFF + 3 * SC_ST;         // 112640
#define NSC 24

__global__ __launch_bounds__(256, 2)
void lstm_persist(const __half* __restrict__ embH,
                  const int* __restrict__ cap,
                  const __half* __restrict__ Wp,
                  const float* __restrict__ pb,
                  const float* __restrict__ c0,
                  __half* __restrict__ hbuf,
                  __half* __restrict__ hlast,
                  const int* __restrict__ cap_len,
                  unsigned int* __restrict__ counter)
{
    extern __shared__ __align__(1024) char smem[];
    uint32_t sb = smem_u32(smem);
    int tid = threadIdx.x, wid = tid >> 5, lid = tid & 31;
    int g = lid >> 2, tig = lid & 3;
    int warpM = (wid & 1) * 64, warpN = (wid >> 1) * 32;
    int bn = blockIdx.x * 128, bm = blockIdx.y * 128;
    int jg0 = bn >> 2;
    int*    stok = (int*)smem;
    float*  pb_s = (float*)(smem + 512);
    int*    cl_s = (int*)(smem + 1024);
    __half* hsm  = (__half*)(smem + SA_OFF);   // overlays stage A0

    uint32_t offA[4], offB[2];
#pragma unroll
    for (int rb = 0; rb < 4; rb++)
        offA[rb] = (warpM + rb * 16 + (lid & 15)) * 144 + (lid >> 4) * 16;
#pragma unroll
    for (int p = 0; p < 2; p++)
        offB[p] = (warpN + p * 16 + ((lid >> 4) << 3) + (lid & 7)) * 144 + ((lid >> 3) & 1) * 16;

    // static epilogue lane mapping (identical math to R9/R10 shuffle epilogue)
    bool ev = (tig & 1) == 0;
    int Jl_base = (warpN >> 2) + (tig >> 1);
    float c_reg[4][4];
#pragma unroll
    for (int rb = 0; rb < 4; rb++) {
        int rrow = warpM + rb * 16 + g + (ev ? 0 : 8);
#pragma unroll
        for (int nb = 0; nb < 4; nb++) {
            int Jl = Jl_base + 2 * nb;
            c_reg[rb][nb] = c0[(size_t)(bm + rrow) * Hc + jg0 + Jl];
        }
    }
    if (tid < 128) {
        cl_s[tid] = cap_len[bm + tid];
        stok[tid] = cap[(size_t)(bm + tid) * Tc + 0];
        pb_s[tid] = pb[bn + tid];
    }
    __syncthreads();

    auto load_sc = [&](int tp, int sc) {
        int s = sc % 3;
        uint32_t aB = sb + SA_OFF + s * SC_ST;
        uint32_t bB = sb + SB_OFF + s * SC_ST;
        const __half* hin = hbuf + (size_t)(tp & 1) * (Bc * Hc);
        bool emb = (sc < 8);
        int kb = emb ? sc * 64 : (sc - 8) * 64;   // emb: 0..448 of E; h: 0..960 of H
#pragma unroll
        for (int i = 0; i < 4; i++) {              // A: 128 rows x 128B
            int seg = tid + i * 256;
            int m = seg >> 3, sg = seg & 7;
            const __half* src = emb
                ? embH + (size_t)stok[m] * Ec + kb + sg * 8
                : hin + (size_t)(bm + m) * Hc + kb + sg * 8;
            CP_ASYNC16(aB + m * 144 + sg * 16, src);
        }
        int kk = emb ? (Hc + kb) : kb;
#pragma unroll
        for (int i = 0; i < 4; i++) {              // B: 128 rows x 128B
            int seg = tid + i * 256;
            int n = seg >> 3, sg = seg & 7;
            CP_ASYNC16(bB + n * 144 + sg * 16,
                       Wp + (size_t)(bn + n) * (Hc + Ec) + kk + sg * 8);
        }
    };

    for (int t = 0; t < Tc; t++) {
        // prologue: 2 embed superchunks
        load_sc(t, 0); CP_COMMIT();
        load_sc(t, 1); CP_COMMIT();

        float acc[4][4][4];
#pragma unroll
        for (int i = 0; i < 4; i++)
#pragma unroll
            for (int j = 0; j < 4; j++)
#pragma unroll
                for (int q = 0; q < 4; q++) acc[i][j][q] = 0.f;

        for (int sc = 0; sc < NSC; sc++) {
            if (sc == 6 && tid == 0) {  // before first h-superchunk load (SC8 issued here)
                unsigned int target = (unsigned int)(NCTA * t);
                unsigned int v;
                do {
                    asm volatile("ld.acquire.gpu.global.u32 %0, [%1];"
                                 : "=r"(v) : "l"(counter) : "memory");
                } while (v < target);
            }
            if (sc == 12 && t + 1 < Tc && tid < 128)
                stok[tid] = cap[(size_t)(bm + tid) * Tc + t + 1];
            CP_WAIT1();
            __syncthreads();
            if (sc + 2 < NSC) load_sc(t, sc + 2);
            CP_COMMIT();                 // unconditional: empty tail groups drain real data
            int s = sc % 3;
            uint32_t aB = sb + SA_OFF + s * SC_ST;
            uint32_t bB = sb + SB_OFF + s * SC_ST;
#pragma unroll
            for (int k16 = 0; k16 < 4; k16++) {
                uint32_t afr[4][4], bfr[2][4];
#pragma unroll
                for (int rb = 0; rb < 4; rb++) ldsm_x4(afr[rb], aB + offA[rb] + k16 * 32);
#pragma unroll
                for (int p = 0; p < 2; p++) ldsm_x4(bfr[p], bB + offB[p] + k16 * 32);
#pragma unroll
                for (int rb = 0; rb < 4; rb++) {
                    mma_f16(acc[rb][0], afr[rb], &bfr[0][0]);
                    mma_f16(acc[rb][1], afr[rb], &bfr[0][2]);
                    mma_f16(acc[rb][2], afr[rb], &bfr[1][0]);
                    mma_f16(acc[rb][3], afr[rb], &bfr[1][2]);
                }
            }
        }

        // epilogue: shuffle gates to (rrow, Jl) lanes; c in registers; stage h only
        __syncthreads();   // all warps done with stages; stage A0 (hsm) safe to reuse
        __half* hout = hbuf + (size_t)((t + 1) & 1) * (Bc * Hc);
#pragma unroll
        for (int rb = 0; rb < 4; rb++) {
            int r0 = warpM + rb * 16 + g;
            int rrow = ev ? r0 : (r0 + 8);
#pragma unroll
            for (int nb = 0; nb < 4; nb++) {
                float v0 = acc[rb][nb][0], v1 = acc[rb][nb][1];
                float v2 = acc[rb][nb][2], v3 = acc[rb][nb][3];
                float x = ev ? v2 : v0, y = ev ? v3 : v1;
                float px = __shfl_xor_sync(0xffffffffu, x, 1);
                float py = __shfl_xor_sync(0xffffffffu, y, 1);
                float gi = ev ? v0 : px, gf = ev ? v1 : py;
                float gg = ev ? px : v2, go = ev ? py : v3;
                int Jl = Jl_base + 2 * nb;
                float4 pbv = *(const float4*)(pb_s + 4 * Jl);
                float si = fsig(gi + pbv.x);
                float sf = fsig(gf + pbv.y);
                float tg = ftanh(gg + pbv.z);
                float so = fsig(go + pbv.w);
                float cn = sf * c_reg[rb][nb] + si * tg;
                c_reg[rb][nb] = cn;
                hsm[rrow * 34 + Jl] = __float2half_rn(so * ftanh(cn));
            }
        }
        __syncthreads();
        for (int idx = tid; idx < 128 * 32; idx += 256) {
            int row = idx >> 5, jl = idx & 31;
            __half hv = hsm[row * 34 + jl];
            size_t off = (size_t)(bm + row) * Hc + jg0 + jl;
            hout[off] = hv;
            if (cl_s[row] - 1 == t) hlast[off] = hv;
        }
        __syncthreads();
        if (tid == 0)
            asm volatile("red.release.gpu.global.add.u32 [%0], %1;"
                         :: "l"(counter), "r"(1u) : "memory");
    }
}

// ---------------- launch ----------------
extern "C" void kernel_launch(void* const* d_in, const int* in_sizes, int n_in,
                              void* d_out, int out_size) {
    const int*   cap     = (const int*)  d_in[0];
    const int*   cap_len = (const int*)  d_in[1];
    const float* feat    = (const float*)d_in[2];
    const float* embed   = (const float*)d_in[3];
    const float* W_ih    = (const float*)d_in[4];
    const float* W_hh    = (const float*)d_in[5];
    const float* b_ih    = (const float*)d_in[6];
    const float* b_hh    = (const float*)d_in[7];
    const float* v_ih0   = (const float*)d_in[8];
    const float* g_ih0   = (const float*)d_in[9];
    const float* b_ih0   = (const float*)d_in[10];
    const float* v_ic0   = (const float*)d_in[11];
    const float* g_ic0   = (const float*)d_in[12];
    const float* b_ic0   = (const float*)d_in[13];
    const float* v_mu    = (const float*)d_in[14];
    const float* g_mu    = (const float*)d_in[15];
    const float* b_mu    = (const float*)d_in[16];
    const float* v_s2    = (const float*)d_in[17];
    const float* g_s2    = (const float*)d_in[18];
    const float* b_s2    = (const float*)d_in[19];
    float* out = (float*)d_out;

    __half *Wcat, *Wocat, *Wp, *hbuf, *hl, *embH, *ftH;
    float *bcat, *bocat, *pb, *c0;
    unsigned int* counter;
    cudaGetSymbolAddress((void**)&Wcat,    g_Wcat);
    cudaGetSymbolAddress((void**)&bcat,    g_bcat);
    cudaGetSymbolAddress((void**)&Wocat,   g_Wocat);
    cudaGetSymbolAddress((void**)&bocat,   g_bocat);
    cudaGetSymbolAddress((void**)&Wp,      g_Wp);
    cudaGetSymbolAddress((void**)&pb,      g_pb);
    cudaGetSymbolAddress((void**)&hbuf,    g_hbuf);
    cudaGetSymbolAddress((void**)&c0,      g_c0);
    cudaGetSymbolAddress((void**)&hl,      g_hl);
    cudaGetSymbolAddress((void**)&embH,    g_embH);
    cudaGetSymbolAddress((void**)&ftH,     g_ftH);
    cudaGetSymbolAddress((void**)&counter, g_counter);

    cudaFuncSetAttribute(hgemm,        cudaFuncAttributeMaxDynamicSharedMemorySize, SMEM_G);
    cudaFuncSetAttribute(lstm_persist, cudaFuncAttributeMaxDynamicSharedMemorySize, SMEM_P);

    cudaMemsetAsync(counter, 0, sizeof(unsigned int));

    wn_kernel<<<Hc, 256>>>(v_ih0, g_ih0, Wcat,            Ac);
    wn_kernel<<<Hc, 256>>>(v_ic0, g_ic0, Wcat + Hc * Ac,  Ac);
    wn_kernel<<<Lc, 256>>>(v_mu,  g_mu,  Wocat,           Hc);
    wn_kernel<<<Lc, 256>>>(v_s2,  g_s2,  Wocat + Lc * Hc, Hc);
    pack2<<<(2 * Hc + 255) / 256, 256>>>(b_ih0, b_ic0, bcat, Hc);
    pack2<<<(2 * Lc + 255) / 256, 256>>>(b_mu,  b_s2,  bocat, Lc);
    permute_kernel<<<Nw, 256>>>(W_hh, W_ih, b_ih, b_hh, Wp, pb);
    half_copy<<<(Vc * Ec + 255) / 256, 256>>>(embed, embH, Vc * Ec);
    half_copy<<<(Bc * Ac + 255) / 256, 256>>>(feat, ftH, Bc * Ac);

    // init: h0 (fp16, into hbuf[0]) and c0 (fp32), fused N=2048
    {
        dim3 grid(2 * Hc / 128, Bc / 128);
        hgemm<<<grid, 256, SMEM_G>>>(ftH, Ac, Ac / 32, Wcat, Ac, bcat,
                                     (float*)hbuf, Hc, 1, c0, Hc, 0, Hc);
    }

    // recurrence: persistent kernel, 24 K=64 superchunks/step, c in registers
    {
        dim3 grid(Nw / 128, Bc / 128);       // (32, 8) = 256 CTAs, 2/SM
        lstm_persist<<<grid, 256, SMEM_P>>>(embH, cap, Wp, pb, c0, hbuf, hl, cap_len, counter);
    }

    // outputs: mu and sigma2 fused, N=512
    {
        dim3 grid(2 * Lc / 128, Bc / 128);
        hgemm<<<grid, 256, SMEM_G>>>(hl, Hc, Hc / 32, Wocat, Hc, bocat,
                                     out, Lc, 0, out + Bc * Lc, Lc, 0, Lc);
    }
}

// round 14
// speedup vs baseline: 1.2799x; 1.0490x over previous
#include <cuda_runtime.h>
#include <cuda_fp16.h>
#include <cstdint>
#include <math.h>

// ---------------- problem constants ----------------
#define Bc 1024   // batch
#define Tc 40     // timesteps
#define Ec 512    // embed dim
#define Hc 1024   // hidden
#define Lc 256    // latent out
#define Ac 2048   // feature dim
#define Vc 30000  // vocab
#define Nw 4096   // 4*H
#define NCTA 256

// ---------------- device scratch (no allocation) ----------------
__device__ __half g_Wcat [2 * Hc * Ac];
__device__ float  g_bcat [2 * Hc];
__device__ __half g_Wocat[2 * Lc * Hc];
__device__ float  g_bocat[2 * Lc];
__device__ __align__(128) __half g_WpT[Nw * (Hc + Ec)];  // tiled+swizzled weights
__device__ float  g_pb   [Nw];
__device__ __half g_hbuf [2][Bc * Hc];
__device__ float  g_c0   [Bc * Hc];
__device__ __half g_hl   [Bc * Hc];
__device__ __half g_embH [Vc * Ec];
__device__ __half g_ftH  [Bc * Ac];
__device__ unsigned int g_counter;

// ---------------- helpers ----------------
__device__ __forceinline__ uint32_t smem_u32(const void* p) {
    uint32_t a;
    asm("{ .reg .u64 t; cvta.to.shared.u64 t, %1; cvt.u32.u64 %0, t; }" : "=r"(a) : "l"(p));
    return a;
}
#define CP_ASYNC16(dst, src) \
    asm volatile("cp.async.cg.shared.global [%0], [%1], 16;" :: "r"(dst), "l"(src))
#define CP_COMMIT() asm volatile("cp.async.commit_group;" ::: "memory")
#define CP_WAIT2()  asm volatile("cp.async.wait_group 2;" ::: "memory")
#define CP_WAIT1()  asm volatile("cp.async.wait_group 1;" ::: "memory")

#define MBARRIER_INIT(addr, cnt) \
    asm volatile("mbarrier.init.shared.b64 [%0], %1;" :: "r"(addr), "r"(cnt) : "memory")
#define MBARRIER_EXPECT_TX(addr, bytes) \
    asm volatile("mbarrier.arrive.expect_tx.shared.b64 _, [%0], %1;" :: "r"(addr), "r"(bytes) : "memory")
#define MBARRIER_WAIT_PARITY(addr, par) do {                                        \
    uint32_t _m = (addr), _p = (par), _d;                                           \
    asm volatile("{ .reg .pred p; mbarrier.try_wait.parity.acquire.cta.shared::cta.b64 p, [%1], %2; selp.b32 %0,1,0,p; }" \
        : "=r"(_d) : "r"(_m), "r"(_p) : "memory");                                  \
    if (!_d) {                                                                      \
        asm volatile("{ .reg .pred P1; WL_%=: mbarrier.try_wait.parity.acquire.cta.shared::cta.b64 P1, [%0], %1, 0x989680; @P1 bra.uni WD_%=; bra.uni WL_%=; WD_%=: }" \
            :: "r"(_m), "r"(_p) : "memory");                                        \
    }                                                                               \
} while (0)
#define TMA_BULK(dst, src, bytes, mbar) \
    asm volatile("cp.async.bulk.shared::cta.global.mbarrier::complete_tx::bytes [%0], [%1], %2, [%3];" \
        :: "r"(dst), "l"(src), "r"(bytes), "r"(mbar) : "memory")

__device__ __forceinline__ void mma_f16(float* d, const uint32_t* a, const uint32_t* b) {
    asm volatile(
        "mma.sync.aligned.m16n8k16.row.col.f32.f16.f16.f32 "
        "{%0,%1,%2,%3}, {%4,%5,%6,%7}, {%8,%9}, {%0,%1,%2,%3};"
        : "+f"(d[0]), "+f"(d[1]), "+f"(d[2]), "+f"(d[3])
        : "r"(a[0]), "r"(a[1]), "r"(a[2]), "r"(a[3]), "r"(b[0]), "r"(b[1]));
}
__device__ __forceinline__ void ldsm_x4(uint32_t* r, uint32_t addr) {
    asm volatile("ldmatrix.sync.aligned.m8n8.x4.shared.b16 {%0,%1,%2,%3}, [%4];"
        : "=r"(r[0]), "=r"(r[1]), "=r"(r[2]), "=r"(r[3]) : "r"(addr));
}
__device__ __forceinline__ float fex2(float x) { float r; asm("ex2.approx.f32 %0, %1;" : "=f"(r) : "f"(x)); return r; }
__device__ __forceinline__ float frcp(float x) { float r; asm("rcp.approx.f32 %0, %1;" : "=f"(r) : "f"(x)); return r; }
__device__ __forceinline__ float fsig(float x)  { return frcp(1.f + fex2(-1.4426950408889634f * x)); }
__device__ __forceinline__ float ftanh(float x) { return 1.f - 2.f * frcp(1.f + fex2(2.8853900817779268f * x)); }

// ---------------- prep kernels ----------------
__global__ void wn_kernel(const float* __restrict__ v, const float* __restrict__ g,
                          __half* __restrict__ W, int cols) {
    int r = blockIdx.x;
    const float* vr = v + (size_t)r * cols;
    float s = 0.f;
    for (int c = threadIdx.x; c < cols; c += blockDim.x) { float x = vr[c]; s += x * x; }
    __shared__ float sh[32];
    for (int o = 16; o > 0; o >>= 1) s += __shfl_down_sync(0xffffffffu, s, o);
    if ((threadIdx.x & 31) == 0) sh[threadIdx.x >> 5] = s;
    __syncthreads();
    if (threadIdx.x < 32) {
        float t = (threadIdx.x < (blockDim.x >> 5)) ? sh[threadIdx.x] : 0.f;
        for (int o = 16; o > 0; o >>= 1) t += __shfl_down_sync(0xffffffffu, t, o);
        if (threadIdx.x == 0) sh[0] = t;
    }
    __syncthreads();
    float scale = g[r] / sqrtf(sh[0]);
    __half* Wr = W + (size_t)r * cols;
    for (int c = threadIdx.x; c < cols; c += blockDim.x) Wr[c] = __float2half_rn(vr[c] * scale);
}

// pack LSTM weights into tiled+swizzled layout:
// tile(bnT, sc) = 16KB, rows = permuted gate rows (local), cols = 64 K-vals.
// sc 0..7 = W_ih (E), sc 8..23 = W_hh (H).
__global__ void permute_tiled(const float* __restrict__ Whh, const float* __restrict__ Wih,
                              const float* __restrict__ bih, const float* __restrict__ bhh,
                              __half* __restrict__ WpT, float* __restrict__ pb) {
    int n = blockIdx.x;              // original row 0..4095
    int gt = n >> 10, j = n & 1023;
    int np = (j << 2) | gt;
    int bnT = np >> 7, nl = np & 127;
    char* basep = (char*)WpT;
    const float* s1 = Whh + (size_t)n * Hc;
    const float* s2 = Wih + (size_t)n * Ec;
    for (int k = threadIdx.x; k < Hc; k += blockDim.x) {       // hidden part
        int sc = 8 + (k >> 6), c = k & 63;
        size_t tb = ((size_t)(bnT * 24 + sc)) << 14;
        uint32_t off = nl * 128 + c * 2;
        off ^= (off >> 3) & 0x70;
        *(__half*)(basep + tb + off) = __float2half_rn(s1[k]);
    }
    for (int k = threadIdx.x; k < Ec; k += blockDim.x) {       // embed part
        int sc = k >> 6, c = k & 63;
        size_t tb = ((size_t)(bnT * 24 + sc)) << 14;
        uint32_t off = nl * 128 + c * 2;
        off ^= (off >> 3) & 0x70;
        *(__half*)(basep + tb + off) = __float2half_rn(s2[k]);
    }
    if (threadIdx.x == 0) pb[np] = bih[n] + bhh[n];
}

__global__ void half_copy(const float* __restrict__ src, __half* __restrict__ dst, int n) {
    int i = blockIdx.x * blockDim.x + threadIdx.x;
    if (i < n) dst[i] = __float2half_rn(src[i]);
}

__global__ void pack2(const float* __restrict__ a, const float* __restrict__ b,
                      float* __restrict__ dst, int n) {
    int i = blockIdx.x * blockDim.x + threadIdx.x;
    if (i < n) dst[i] = a[i];
    else if (i < 2 * n) dst[i] = b[i - n];
}

// ---------------- fp16 mma.sync GEMM (init / output projections) — R8-proven ----------------
static constexpr int ST    = 128 * 80;
static constexpr int A_OFF = 1024;
static constexpr int B_OFF = A_OFF + 4 * ST;
static constexpr int SMEM_G = B_OFF + 4 * ST;             // 82944

__global__ __launch_bounds__(256, 2)
void hgemm(const __half* __restrict__ A1, int lda1, int kc1,
           const __half* __restrict__ Bw, int ldb,
           const float* __restrict__ bias,
           float* __restrict__ C1, int ldc1, int half1,
           float* __restrict__ C2, int ldc2, int half2, int ncut)
{
    extern __shared__ __align__(1024) char smem[];
    uint32_t sb = smem_u32(smem);
    int tid = threadIdx.x, wid = tid >> 5, lid = tid & 31;
    int g = lid >> 2, tig = lid & 3;
    int warpM = (wid & 1) * 64, warpN = (wid >> 1) * 32;
    int bm = blockIdx.y * 128, bn = blockIdx.x * 128;
    const int NC = kc1;

    uint32_t offA[4], offB[2];
#pragma unroll
    for (int rb = 0; rb < 4; rb++)
        offA[rb] = (warpM + rb * 16 + (lid & 15)) * 80 + (lid >> 4) * 16;
#pragma unroll
    for (int p = 0; p < 2; p++)
        offB[p] = (warpN + p * 16 + ((lid >> 4) << 3) + (lid & 7)) * 80 + ((lid >> 3) & 1) * 16;

    float acc[4][4][4];
#pragma unroll
    for (int i = 0; i < 4; i++)
#pragma unroll
        for (int j = 0; j < 4; j++)
#pragma unroll
            for (int q = 0; q < 4; q++) acc[i][j][q] = 0.f;

    auto load_chunk = [&](int c, int s) {
        uint32_t aB = sb + A_OFF + s * ST;
        uint32_t bB = sb + B_OFF + s * ST;
#pragma unroll
        for (int i = 0; i < 2; i++) {
            int seg = tid + i * 256;
            int m = seg >> 2, sg = seg & 3;
            CP_ASYNC16(aB + m * 80 + sg * 16, A1 + (size_t)(bm + m) * lda1 + c * 32 + sg * 8);
        }
#pragma unroll
        for (int i = 0; i < 2; i++) {
            int seg = tid + i * 256;
            int n = seg >> 2, sg = seg & 3;
            CP_ASYNC16(bB + n * 80 + sg * 16, Bw + (size_t)(bn + n) * ldb + c * 32 + sg * 8);
        }
    };

    for (int p = 0; p < 3; p++) { load_chunk(p, p); CP_COMMIT(); }

    for (int c = 0; c < NC; c++) {
        int s = c & 3;
        CP_WAIT2();
        __syncthreads();
        if (c + 3 < NC) load_chunk(c + 3, (c + 3) & 3);
        CP_COMMIT();
        uint32_t aB = sb + A_OFF + s * ST;
        uint32_t bB = sb + B_OFF + s * ST;
#pragma unroll
        for (int k16 = 0; k16 < 2; k16++) {
            uint32_t afr[4][4], bfr[2][4];
#pragma unroll
            for (int rb = 0; rb < 4; rb++) ldsm_x4(afr[rb], aB + offA[rb] + k16 * 32);
#pragma unroll
            for (int p = 0; p < 2; p++) ldsm_x4(bfr[p], bB + offB[p] + k16 * 32);
#pragma unroll
            for (int rb = 0; rb < 4; rb++) {
                mma_f16(acc[rb][0], afr[rb], &bfr[0][0]);
                mma_f16(acc[rb][1], afr[rb], &bfr[0][2]);
                mma_f16(acc[rb][2], afr[rb], &bfr[1][0]);
                mma_f16(acc[rb][3], afr[rb], &bfr[1][2]);
            }
        }
    }

    float* Cd; int cb, ldc, hf;
    if (bn < ncut) { Cd = C1; cb = bn;        ldc = ldc1; hf = half1; }
    else           { Cd = C2; cb = bn - ncut; ldc = ldc2; hf = half2; }
#pragma unroll
    for (int rb = 0; rb < 4; rb++) {
#pragma unroll
        for (int nb = 0; nb < 4; nb++) {
            int coll = warpN + nb * 8 + 2 * tig;
            int col = cb + coll;
            int r0 = bm + warpM + rb * 16 + g;
            float b0 = bias[bn + coll], b1 = bias[bn + coll + 1];
            float v0 = acc[rb][nb][0] + b0, v1 = acc[rb][nb][1] + b1;
            float v2 = acc[rb][nb][2] + b0, v3 = acc[rb][nb][3] + b1;
            if (hf) {
                __half* Ch = (__half*)Cd;
                *(__half2*)(Ch + (size_t)r0 * ldc + col)       = __floats2half2_rn(v0, v1);
                *(__half2*)(Ch + (size_t)(r0 + 8) * ldc + col) = __floats2half2_rn(v2, v3);
            } else {
                *(float2*)(Cd + (size_t)r0 * ldc + col)       = make_float2(v0, v1);
                *(float2*)(Cd + (size_t)(r0 + 8) * ldc + col) = make_float2(v2, v3);
            }
        }
    }
}

// ---------------- persistent LSTM: B tiles via cp.async.bulk (TMA), A via cp.async ----------------
// smem: [0,512) stok, [512,1024) pb_s, [1024,1536) cl_s, [1536,1560) mbar[3],
//       [2048, +3*18432) A stages, then 3*16384 B stages (swizzled, 128B pitch).
static constexpr int A_ST   = 128 * 144;                  // 18432
static constexpr int B_STB  = 128 * 128;                  // 16384
static constexpr int MB_OFF = 1536;
static constexpr int SA_OFF = 2048;
static constexpr int SBB_OFF = SA_OFF + 3 * A_ST;         // 57344
static constexpr int SMEM_P  = SBB_OFF + 3 * B_STB;       // 106496
#define NSC 24

__global__ __launch_bounds__(256, 2)
void lstm_persist(const __half* __restrict__ embH,
                  const int* __restrict__ cap,
                  const __half* __restrict__ WpT,
                  const float* __restrict__ pb,
                  const float* __restrict__ c0,
                  __half* __restrict__ hbuf,
                  __half* __restrict__ hlast,
                  const int* __restrict__ cap_len,
                  unsigned int* __restrict__ counter)
{
    extern __shared__ __align__(1024) char smem[];
    uint32_t sb = smem_u32(smem);
    int tid = threadIdx.x, wid = tid >> 5, lid = tid & 31;
    int g = lid >> 2, tig = lid & 3;
    int warpM = (wid & 1) * 64, warpN = (wid >> 1) * 32;
    int bn = blockIdx.x * 128, bm = blockIdx.y * 128;
    int jg0 = bn >> 2;
    int*    stok = (int*)smem;
    float*  pb_s = (float*)(smem + 512);
    int*    cl_s = (int*)(smem + 1024);
    __half* hsm  = (__half*)(smem + SA_OFF);   // overlays stage A0

    // A fragment offsets (144B pitch, padded — conflict-free)
    uint32_t offA[4];
#pragma unroll
    for (int rb = 0; rb < 4; rb++)
        offA[rb] = (warpM + rb * 16 + (lid & 15)) * 144 + (lid >> 4) * 16;
    // B fragment offsets: 128B pitch, SW128 swizzle applied per access:
    // addr = rowbase + ((cb0 + k16*32) ^ xmask)
    uint32_t rowB[2], xmB[2];
    uint32_t cb0 = ((lid >> 3) & 1) * 16;
#pragma unroll
    for (int p = 0; p < 2; p++) {
        int row = warpN + p * 16 + ((lid >> 4) << 3) + (lid & 7);
        rowB[p] = row * 128;
        xmB[p]  = (row & 7) * 16;
    }

    bool ev = (tig & 1) == 0;
    int Jl_base = (warpN >> 2) + (tig >> 1);
    float c_reg[4][4];
#pragma unroll
    for (int rb = 0; rb < 4; rb++) {
        int rrow = warpM + rb * 16 + g + (ev ? 0 : 8);
#pragma unroll
        for (int nb = 0; nb < 4; nb++) {
            int Jl = Jl_base + 2 * nb;
            c_reg[rb][nb] = c0[(size_t)(bm + rrow) * Hc + jg0 + Jl];
        }
    }
    if (tid < 128) {
        cl_s[tid] = cap_len[bm + tid];
        stok[tid] = cap[(size_t)(bm + tid) * Tc + 0];
        pb_s[tid] = pb[bn + tid];
    }
    if (tid == 0) {
#pragma unroll
        for (int i = 0; i < 3; i++) MBARRIER_INIT(sb + MB_OFF + i * 8, 1);
    }
    __syncthreads();

    auto load_sc = [&](int tp, int sc) {
        int s = sc % 3;
        uint32_t aB = sb + SA_OFF + s * A_ST;
        const __half* hin = hbuf + (size_t)(tp & 1) * (Bc * Hc);
        bool emb = (sc < 8);
        int kb = emb ? sc * 64 : (sc - 8) * 64;
#pragma unroll
        for (int i = 0; i < 4; i++) {              // A: 128 rows x 128B via cp.async
            int seg = tid + i * 256;
            int m = seg >> 3, sg = seg & 7;
            const __half* src = emb
                ? embH + (size_t)stok[m] * Ec + kb + sg * 8
                : hin + (size_t)(bm + m) * Hc + kb + sg * 8;
            CP_ASYNC16(aB + m * 144 + sg * 16, src);
        }
        if (tid == 0) {                            // B: one 16KB bulk copy
            uint32_t mb = sb + MB_OFF + s * 8;
            MBARRIER_EXPECT_TX(mb, B_STB);
            const char* src = (const char*)WpT + (((size_t)blockIdx.x * 24 + sc) << 14);
            TMA_BULK(sb + SBB_OFF + s * B_STB, src, B_STB, mb);
        }
    };

    for (int t = 0; t < Tc; t++) {
        load_sc(t, 0); CP_COMMIT();
        load_sc(t, 1); CP_COMMIT();

        float acc[4][4][4];
#pragma unroll
        for (int i = 0; i < 4; i++)
#pragma unroll
            for (int j = 0; j < 4; j++)
#pragma unroll
                for (int q = 0; q < 4; q++) acc[i][j][q] = 0.f;

        for (int sc = 0; sc < NSC; sc++) {
            if (sc == 6 && tid == 0) {  // before first h-superchunk load (SC8)
                unsigned int target = (unsigned int)(NCTA * t);
                unsigned int v;
                do {
                    asm volatile("ld.acquire.gpu.global.u32 %0, [%1];"
                                 : "=r"(v) : "l"(counter) : "memory");
                } while (v < target);
            }
            if (sc == 12 && t + 1 < Tc && tid < 128)
                stok[tid] = cap[(size_t)(bm + tid) * Tc + t + 1];
            CP_WAIT1();                                           // A data for sc
            MBARRIER_WAIT_PARITY(sb + MB_OFF + (sc % 3) * 8, (sc / 3) & 1);  // B data
            __syncthreads();
            if (sc + 2 < NSC) load_sc(t, sc + 2);
            CP_COMMIT();                 // unconditional (tail-drain)
            int s = sc % 3;
            uint32_t aB = sb + SA_OFF + s * A_ST;
            uint32_t bB = sb + SBB_OFF + s * B_STB;
#pragma unroll
            for (int k16 = 0; k16 < 4; k16++) {
                uint32_t afr[4][4], bfr[2][4];
#pragma unroll
                for (int rb = 0; rb < 4; rb++) ldsm_x4(afr[rb], aB + offA[rb] + k16 * 32);
#pragma unroll
                for (int p = 0; p < 2; p++)
                    ldsm_x4(bfr[p], bB + rowB[p] + ((cb0 + k16 * 32) ^ xmB[p]));
#pragma unroll
                for (int rb = 0; rb < 4; rb++) {
                    mma_f16(acc[rb][0], afr[rb], &bfr[0][0]);
                    mma_f16(acc[rb][1], afr[rb], &bfr[0][2]);
                    mma_f16(acc[rb][2], afr[rb], &bfr[1][0]);
                    mma_f16(acc[rb][3], afr[rb], &bfr[1][2]);
                }
            }
        }

        // epilogue: shuffle gates to (rrow, Jl) lanes; c in registers; stage h only
        __syncthreads();
        __half* hout = hbuf + (size_t)((t + 1) & 1) * (Bc * Hc);
#pragma unroll
        for (int rb = 0; rb < 4; rb++) {
            int r0 = warpM + rb * 16 + g;
            int rrow = ev ? r0 : (r0 + 8);
#pragma unroll
            for (int nb = 0; nb < 4; nb++) {
                float v0 = acc[rb][nb][0], v1 = acc[rb][nb][1];
                float v2 = acc[rb][nb][2], v3 = acc[rb][nb][3];
                float x = ev ? v2 : v0, y = ev ? v3 : v1;
                float px = __shfl_xor_sync(0xffffffffu, x, 1);
                float py = __shfl_xor_sync(0xffffffffu, y, 1);
                float gi = ev ? v0 : px, gf = ev ? v1 : py;
                float gg = ev ? px : v2, go = ev ? py : v3;
                int Jl = Jl_base + 2 * nb;
                float4 pbv = *(const float4*)(pb_s + 4 * Jl);
                float si = fsig(gi + pbv.x);
                float sf = fsig(gf + pbv.y);
                float tg = ftanh(gg + pbv.z);
                float so = fsig(go + pbv.w);
                float cn = sf * c_reg[rb][nb] + si * tg;
                c_reg[rb][nb] = cn;
                hsm[rrow * 34 + Jl] = __float2half_rn(so * ftanh(cn));
            }
        }
        __syncthreads();
        for (int idx = tid; idx < 128 * 32; idx += 256) {
            int row = idx >> 5, jl = idx & 31;
            __half hv = hsm[row * 34 + jl];
            size_t off = (size_t)(bm + row) * Hc + jg0 + jl;
            hout[off] = hv;
            if (cl_s[row] - 1 == t) hlast[off] = hv;
        }
        __syncthreads();
        if (tid == 0)
            asm volatile("red.release.gpu.global.add.u32 [%0], %1;"
                         :: "l"(counter), "r"(1u) : "memory");
    }
}

// ---------------- launch ----------------
extern "C" void kernel_launch(void* const* d_in, const int* in_sizes, int n_in,
                              void* d_out, int out_size) {
    const int*   cap     = (const int*)  d_in[0];
    const int*   cap_len = (const int*)  d_in[1];
    const float* feat    = (const float*)d_in[2];
    const float* embed   = (const float*)d_in[3];
    const float* W_ih    = (const float*)d_in[4];
    const float* W_hh    = (const float*)d_in[5];
    const float* b_ih    = (const float*)d_in[6];
    const float* b_hh    = (const float*)d_in[7];
    const float* v_ih0   = (const float*)d_in[8];
    const float* g_ih0   = (const float*)d_in[9];
    const float* b_ih0   = (const float*)d_in[10];
    const float* v_ic0   = (const float*)d_in[11];
    const float* g_ic0   = (const float*)d_in[12];
    const float* b_ic0   = (const float*)d_in[13];
    const float* v_mu    = (const float*)d_in[14];
    const float* g_mu    = (const float*)d_in[15];
    const float* b_mu    = (const float*)d_in[16];
    const float* v_s2    = (const float*)d_in[17];
    const float* g_s2    = (const float*)d_in[18];
    const float* b_s2    = (const float*)d_in[19];
    float* out = (float*)d_out;

    __half *Wcat, *Wocat, *WpT, *hbuf, *hl, *embH, *ftH;
    float *bcat, *bocat, *pb, *c0;
    unsigned int* counter;
    cudaGetSymbolAddress((void**)&Wcat,    g_Wcat);
    cudaGetSymbolAddress((void**)&bcat,    g_bcat);
    cudaGetSymbolAddress((void**)&Wocat,   g_Wocat);
    cudaGetSymbolAddress((void**)&bocat,   g_bocat);
    cudaGetSymbolAddress((void**)&WpT,     g_WpT);
    cudaGetSymbolAddress((void**)&pb,      g_pb);
    cudaGetSymbolAddress((void**)&hbuf,    g_hbuf);
    cudaGetSymbolAddress((void**)&c0,      g_c0);
    cudaGetSymbolAddress((void**)&hl,      g_hl);
    cudaGetSymbolAddress((void**)&embH,    g_embH);
    cudaGetSymbolAddress((void**)&ftH,     g_ftH);
    cudaGetSymbolAddress((void**)&counter, g_counter);

    cudaFuncSetAttribute(hgemm,        cudaFuncAttributeMaxDynamicSharedMemorySize, SMEM_G);
    cudaFuncSetAttribute(lstm_persist, cudaFuncAttributeMaxDynamicSharedMemorySize, SMEM_P);

    cudaMemsetAsync(counter, 0, sizeof(unsigned int));

    wn_kernel<<<Hc, 256>>>(v_ih0, g_ih0, Wcat,            Ac);
    wn_kernel<<<Hc, 256>>>(v_ic0, g_ic0, Wcat + Hc * Ac,  Ac);
    wn_kernel<<<Lc, 256>>>(v_mu,  g_mu,  Wocat,           Hc);
    wn_kernel<<<Lc, 256>>>(v_s2,  g_s2,  Wocat + Lc * Hc, Hc);
    pack2<<<(2 * Hc + 255) / 256, 256>>>(b_ih0, b_ic0, bcat, Hc);
    pack2<<<(2 * Lc + 255) / 256, 256>>>(b_mu,  b_s2,  bocat, Lc);
    permute_tiled<<<Nw, 256>>>(W_hh, W_ih, b_ih, b_hh, WpT, pb);
    half_copy<<<(Vc * Ec + 255) / 256, 256>>>(embed, embH, Vc * Ec);
    half_copy<<<(Bc * Ac + 255) / 256, 256>>>(feat, ftH, Bc * Ac);

    // init: h0 (fp16, into hbuf[0]) and c0 (fp32), fused N=2048
    {
        dim3 grid(2 * Hc / 128, Bc / 128);
        hgemm<<<grid, 256, SMEM_G>>>(ftH, Ac, Ac / 32, Wcat, Ac, bcat,
                                     (float*)hbuf, Hc, 1, c0, Hc, 0, Hc);
    }

    // recurrence: persistent kernel, weights via bulk-TMA, A via cp.async
    {
        dim3 grid(Nw / 128, Bc / 128);       // (32, 8) = 256 CTAs, 2/SM
        lstm_persist<<<grid, 256, SMEM_P>>>(embH, cap, WpT, pb, c0, hbuf, hl, cap_len, counter);
    }

    // outputs: mu and sigma2 fused, N=512
    {
        dim3 grid(2 * Lc / 128, Bc / 128);
        hgemm<<<grid, 256, SMEM_G>>>(hl, Hc, Hc / 32, Wocat, Hc, bocat,
                                     out, Lc, 0, out + Bc * Lc, Lc, 0, Lc);
    }
}

// round 15
// speedup vs baseline: 1.4681x; 1.1470x over previous
#include <cuda_runtime.h>
#include <cuda_fp16.h>
#include <cstdint>
#include <math.h>

// ---------------- problem constants ----------------
#define Bc 1024   // batch
#define Tc 40     // timesteps
#define Ec 512    // embed dim
#define Hc 1024   // hidden
#define Lc 256    // latent out
#define Ac 2048   // feature dim
#define Vc 30000  // vocab
#define Nw 4096   // 4*H
#define NCTA 256

// ---------------- device scratch (no allocation) ----------------
__device__ __half g_Wcat [2 * Hc * Ac];
__device__ float  g_bcat [2 * Hc];
__device__ __half g_Wocat[2 * Lc * Hc];
__device__ float  g_bocat[2 * Lc];
__device__ __align__(128) __half g_WpT[Nw * (Hc + Ec)];   // tiled+swizzled weights
__device__ float  g_pb   [Nw];
__device__ __align__(128) __half g_xt [(size_t)Tc * 8 * 8 * 8192];  // gathered embed tiles (42MB)
__device__ __align__(128) __half g_hT [2 * 8 * 16 * 8192];          // tiled h state (4.2MB)
__device__ __half g_h0   [Bc * Hc];      // linear h0 (repacked into g_hT[0])
__device__ float  g_c0   [Bc * Hc];
__device__ __half g_hl   [Bc * Hc];
__device__ __half g_embH [Vc * Ec];
__device__ __half g_ftH  [Bc * Ac];
__device__ unsigned int g_counter;

// ---------------- helpers ----------------
__device__ __forceinline__ uint32_t smem_u32(const void* p) {
    uint32_t a;
    asm("{ .reg .u64 t; cvta.to.shared.u64 t, %1; cvt.u32.u64 %0, t; }" : "=r"(a) : "l"(p));
    return a;
}
#define CP_ASYNC16(dst, src) \
    asm volatile("cp.async.cg.shared.global [%0], [%1], 16;" :: "r"(dst), "l"(src))
#define CP_COMMIT() asm volatile("cp.async.commit_group;" ::: "memory")
#define CP_WAIT2()  asm volatile("cp.async.wait_group 2;" ::: "memory")

#define MBARRIER_INIT(addr, cnt) \
    asm volatile("mbarrier.init.shared.b64 [%0], %1;" :: "r"(addr), "r"(cnt) : "memory")
#define MBARRIER_EXPECT_TX(addr, bytes) \
    asm volatile("mbarrier.arrive.expect_tx.shared.b64 _, [%0], %1;" :: "r"(addr), "r"(bytes) : "memory")
#define MBARRIER_WAIT_PARITY(addr, par) do {                                        \
    uint32_t _m = (addr), _p = (par), _d;                                           \
    asm volatile("{ .reg .pred p; mbarrier.try_wait.parity.acquire.cta.shared::cta.b64 p, [%1], %2; selp.b32 %0,1,0,p; }" \
        : "=r"(_d) : "r"(_m), "r"(_p) : "memory");                                  \
    if (!_d) {                                                                      \
        asm volatile("{ .reg .pred P1; WL_%=: mbarrier.try_wait.parity.acquire.cta.shared::cta.b64 P1, [%0], %1, 0x989680; @P1 bra.uni WD_%=; bra.uni WL_%=; WD_%=: }" \
            :: "r"(_m), "r"(_p) : "memory");                                        \
    }                                                                               \
} while (0)
#define TMA_BULK(dst, src, bytes, mbar) \
    asm volatile("cp.async.bulk.shared::cta.global.mbarrier::complete_tx::bytes [%0], [%1], %2, [%3];" \
        :: "r"(dst), "l"(src), "r"(bytes), "r"(mbar) : "memory")
#define FENCE_ASYNC() asm volatile("fence.proxy.async;" ::: "memory")

__device__ __forceinline__ void mma_f16(float* d, const uint32_t* a, const uint32_t* b) {
    asm volatile(
        "mma.sync.aligned.m16n8k16.row.col.f32.f16.f16.f32 "
        "{%0,%1,%2,%3}, {%4,%5,%6,%7}, {%8,%9}, {%0,%1,%2,%3};"
        : "+f"(d[0]), "+f"(d[1]), "+f"(d[2]), "+f"(d[3])
        : "r"(a[0]), "r"(a[1]), "r"(a[2]), "r"(a[3]), "r"(b[0]), "r"(b[1]));
}
__device__ __forceinline__ void ldsm_x4(uint32_t* r, uint32_t addr) {
    asm volatile("ldmatrix.sync.aligned.m8n8.x4.shared.b16 {%0,%1,%2,%3}, [%4];"
        : "=r"(r[0]), "=r"(r[1]), "=r"(r[2]), "=r"(r[3]) : "r"(addr));
}
__device__ __forceinline__ float fex2(float x) { float r; asm("ex2.approx.f32 %0, %1;" : "=f"(r) : "f"(x)); return r; }
__device__ __forceinline__ float frcp(float x) { float r; asm("rcp.approx.f32 %0, %1;" : "=f"(r) : "f"(x)); return r; }
__device__ __forceinline__ float fsig(float x)  { return frcp(1.f + fex2(-1.4426950408889634f * x)); }
__device__ __forceinline__ float ftanh(float x) { return 1.f - 2.f * frcp(1.f + fex2(2.8853900817779268f * x)); }

// ---------------- prep kernels ----------------
__global__ void wn_kernel(const float* __restrict__ v, const float* __restrict__ g,
                          __half* __restrict__ W, int cols) {
    int r = blockIdx.x;
    const float* vr = v + (size_t)r * cols;
    float s = 0.f;
    for (int c = threadIdx.x; c < cols; c += blockDim.x) { float x = vr[c]; s += x * x; }
    __shared__ float sh[32];
    for (int o = 16; o > 0; o >>= 1) s += __shfl_down_sync(0xffffffffu, s, o);
    if ((threadIdx.x & 31) == 0) sh[threadIdx.x >> 5] = s;
    __syncthreads();
    if (threadIdx.x < 32) {
        float t = (threadIdx.x < (blockDim.x >> 5)) ? sh[threadIdx.x] : 0.f;
        for (int o = 16; o > 0; o >>= 1) t += __shfl_down_sync(0xffffffffu, t, o);
        if (threadIdx.x == 0) sh[0] = t;
    }
    __syncthreads();
    float scale = g[r] / sqrtf(sh[0]);
    __half* Wr = W + (size_t)r * cols;
    for (int c = threadIdx.x; c < cols; c += blockDim.x) Wr[c] = __float2half_rn(vr[c] * scale);
}

// pack LSTM weights into tiled+swizzled layout (tile = [bnT][sc] 16KB; sc0..7=W_ih, 8..23=W_hh)
__global__ void permute_tiled(const float* __restrict__ Whh, const float* __restrict__ Wih,
                              const float* __restrict__ bih, const float* __restrict__ bhh,
                              __half* __restrict__ WpT, float* __restrict__ pb) {
    int n = blockIdx.x;
    int gt = n >> 10, j = n & 1023;
    int np = (j << 2) | gt;
    int bnT = np >> 7, nl = np & 127;
    char* basep = (char*)WpT;
    const float* s1 = Whh + (size_t)n * Hc;
    const float* s2 = Wih + (size_t)n * Ec;
    for (int k = threadIdx.x; k < Hc; k += blockDim.x) {
        int sc = 8 + (k >> 6), c = k & 63;
        size_t tb = ((size_t)(bnT * 24 + sc)) << 14;
        uint32_t off = nl * 128 + c * 2;
        off ^= (off >> 3) & 0x70;
        *(__half*)(basep + tb + off) = __float2half_rn(s1[k]);
    }
    for (int k = threadIdx.x; k < Ec; k += blockDim.x) {
        int sc = k >> 6, c = k & 63;
        size_t tb = ((size_t)(bnT * 24 + sc)) << 14;
        uint32_t off = nl * 128 + c * 2;
        off ^= (off >> 3) & 0x70;
        *(__half*)(basep + tb + off) = __float2half_rn(s2[k]);
    }
    if (threadIdx.x == 0) pb[np] = bih[n] + bhh[n];
}

// gather embeddings into tiled+swizzled per-step tiles: xt[t][bmT][sc][128x64]
// block = 256 threads = 4 rows x 64 col-chunks of 8
__global__ void gather_xt(const __half* __restrict__ embH, const int* __restrict__ cap,
                          __half* __restrict__ xt) {
    int blk = blockIdx.x;                 // 0 .. Tc*Bc/4 - 1
    int r4 = threadIdx.x >> 6;            // 0..3
    int thr = threadIdx.x & 63;           // col chunk
    int gr = blk * 4 + r4;                // global (t,b) row
    int t = gr / Bc, b = gr % Bc;
    int tok = cap[(size_t)b * Tc + t];
    int bmT = b >> 7, rowl = b & 127;
    int c0 = thr * 8, sc = c0 >> 6, c = c0 & 63;
    const char* src = (const char*)(embH + (size_t)tok * Ec + c0);
    char* tb = (char*)xt + ((((size_t)t * 8 + bmT) * 8 + sc) << 14);
    uint32_t off = rowl * 128 + c * 2;
    off ^= (off >> 3) & 0x70;
    *(float4*)(tb + off) = *(const float4*)src;
}

// repack linear h0 -> tiled+swizzled hT[0]
__global__ void repack_h0(const __half* __restrict__ h0, __half* __restrict__ hT) {
    int e = (blockIdx.x * 256 + threadIdx.x) * 8;   // element index, 8 cols per thread
    int b = e >> 10, col = e & 1023;
    int bmT = b >> 7, rowl = b & 127;
    int sc = col >> 6, c = col & 63;
    char* tb = (char*)hT + ((((size_t)bmT) * 16 + sc) << 14);
    uint32_t off = rowl * 128 + c * 2;
    off ^= (off >> 3) & 0x70;
    *(float4*)(tb + off) = *(const float4*)(h0 + (size_t)b * Hc + col);
}

__global__ void half_copy(const float* __restrict__ src, __half* __restrict__ dst, int n) {
    int i = blockIdx.x * blockDim.x + threadIdx.x;
    if (i < n) dst[i] = __float2half_rn(src[i]);
}

__global__ void pack2(const float* __restrict__ a, const float* __restrict__ b,
                      float* __restrict__ dst, int n) {
    int i = blockIdx.x * blockDim.x + threadIdx.x;
    if (i < n) dst[i] = a[i];
    else if (i < 2 * n) dst[i] = b[i - n];
}

// ---------------- fp16 mma.sync GEMM (init / output projections) — R8-proven ----------------
static constexpr int ST    = 128 * 80;
static constexpr int A_OFF = 1024;
static constexpr int B_OFF = A_OFF + 4 * ST;
static constexpr int SMEM_G = B_OFF + 4 * ST;             // 82944

__global__ __launch_bounds__(256, 2)
void hgemm(const __half* __restrict__ A1, int lda1, int kc1,
           const __half* __restrict__ Bw, int ldb,
           const float* __restrict__ bias,
           float* __restrict__ C1, int ldc1, int half1,
           float* __restrict__ C2, int ldc2, int half2, int ncut)
{
    extern __shared__ __align__(1024) char smem[];
    uint32_t sb = smem_u32(smem);
    int tid = threadIdx.x, wid = tid >> 5, lid = tid & 31;
    int g = lid >> 2, tig = lid & 3;
    int warpM = (wid & 1) * 64, warpN = (wid >> 1) * 32;
    int bm = blockIdx.y * 128, bn = blockIdx.x * 128;
    const int NC = kc1;

    uint32_t offA[4], offB[2];
#pragma unroll
    for (int rb = 0; rb < 4; rb++)
        offA[rb] = (warpM + rb * 16 + (lid & 15)) * 80 + (lid >> 4) * 16;
#pragma unroll
    for (int p = 0; p < 2; p++)
        offB[p] = (warpN + p * 16 + ((lid >> 4) << 3) + (lid & 7)) * 80 + ((lid >> 3) & 1) * 16;

    float acc[4][4][4];
#pragma unroll
    for (int i = 0; i < 4; i++)
#pragma unroll
        for (int j = 0; j < 4; j++)
#pragma unroll
            for (int q = 0; q < 4; q++) acc[i][j][q] = 0.f;

    auto load_chunk = [&](int c, int s) {
        uint32_t aB = sb + A_OFF + s * ST;
        uint32_t bB = sb + B_OFF + s * ST;
#pragma unroll
        for (int i = 0; i < 2; i++) {
            int seg = tid + i * 256;
            int m = seg >> 2, sg = seg & 3;
            CP_ASYNC16(aB + m * 80 + sg * 16, A1 + (size_t)(bm + m) * lda1 + c * 32 + sg * 8);
        }
#pragma unroll
        for (int i = 0; i < 2; i++) {
            int seg = tid + i * 256;
            int n = seg >> 2, sg = seg & 3;
            CP_ASYNC16(bB + n * 80 + sg * 16, Bw + (size_t)(bn + n) * ldb + c * 32 + sg * 8);
        }
    };

    for (int p = 0; p < 3; p++) { load_chunk(p, p); CP_COMMIT(); }

    for (int c = 0; c < NC; c++) {
        int s = c & 3;
        CP_WAIT2();
        __syncthreads();
        if (c + 3 < NC) load_chunk(c + 3, (c + 3) & 3);
        CP_COMMIT();
        uint32_t aB = sb + A_OFF + s * ST;
        uint32_t bB = sb + B_OFF + s * ST;
#pragma unroll
        for (int k16 = 0; k16 < 2; k16++) {
            uint32_t afr[4][4], bfr[2][4];
#pragma unroll
            for (int rb = 0; rb < 4; rb++) ldsm_x4(afr[rb], aB + offA[rb] + k16 * 32);
#pragma unroll
            for (int p = 0; p < 2; p++) ldsm_x4(bfr[p], bB + offB[p] + k16 * 32);
#pragma unroll
            for (int rb = 0; rb < 4; rb++) {
                mma_f16(acc[rb][0], afr[rb], &bfr[0][0]);
                mma_f16(acc[rb][1], afr[rb], &bfr[0][2]);
                mma_f16(acc[rb][2], afr[rb], &bfr[1][0]);
                mma_f16(acc[rb][3], afr[rb], &bfr[1][2]);
            }
        }
    }

    float* Cd; int cb, ldc, hf;
    if (bn < ncut) { Cd = C1; cb = bn;        ldc = ldc1; hf = half1; }
    else           { Cd = C2; cb = bn - ncut; ldc = ldc2; hf = half2; }
#pragma unroll
    for (int rb = 0; rb < 4; rb++) {
#pragma unroll
        for (int nb = 0; nb < 4; nb++) {
            int coll = warpN + nb * 8 + 2 * tig;
            int col = cb + coll;
            int r0 = bm + warpM + rb * 16 + g;
            float b0 = bias[bn + coll], b1 = bias[bn + coll + 1];
            float v0 = acc[rb][nb][0] + b0, v1 = acc[rb][nb][1] + b1;
            float v2 = acc[rb][nb][2] + b0, v3 = acc[rb][nb][3] + b1;
            if (hf) {
                __half* Ch = (__half*)Cd;
                *(__half2*)(Ch + (size_t)r0 * ldc + col)       = __floats2half2_rn(v0, v1);
                *(__half2*)(Ch + (size_t)(r0 + 8) * ldc + col) = __floats2half2_rn(v2, v3);
            } else {
                *(float2*)(Cd + (size_t)r0 * ldc + col)       = make_float2(v0, v1);
                *(float2*)(Cd + (size_t)(r0 + 8) * ldc + col) = make_float2(v2, v3);
            }
        }
    }
}

// ---------------- persistent LSTM: ALL tiles via cp.async.bulk ----------------
// smem: [0,512) pb_s, [512,1024) cl_s, [1024,1048) mbar[3], [2048, +3*32768) stages (A|B).
static constexpr int STG    = 32768;                      // 16KB A + 16KB B
static constexpr int MB_OFF = 1024;
static constexpr int SA_OFF = 2048;
static constexpr int SMEM_P = SA_OFF + 3 * STG;           // 100352
#define NSC 24

__global__ __launch_bounds__(256, 2)
void lstm_persist(const __half* __restrict__ xt,
                  const __half* __restrict__ WpT,
                  const float* __restrict__ pb,
                  const float* __restrict__ c0,
                  __half* __restrict__ hT,
                  __half* __restrict__ hlast,
                  const int* __restrict__ cap_len,
                  unsigned int* __restrict__ counter)
{
    extern __shared__ __align__(1024) char smem[];
    uint32_t sb = smem_u32(smem);
    int tid = threadIdx.x, wid = tid >> 5, lid = tid & 31;
    int g = lid >> 2, tig = lid & 3;
    int warpM = (wid & 1) * 64, warpN = (wid >> 1) * 32;
    int bx = blockIdx.x, bmT = blockIdx.y;
    int bn = bx * 128, bm = bmT * 128;
    int jg0 = bn >> 2;
    float* pb_s = (float*)smem;
    int*   cl_s = (int*)(smem + 512);

    // A fragment addressing (128B pitch, SW128 swizzle)
    uint32_t rowA[4], xmA[4];
    uint32_t cbA = (lid >> 4) * 16;
#pragma unroll
    for (int rb = 0; rb < 4; rb++) {
        int row = warpM + rb * 16 + (lid & 15);
        rowA[rb] = row * 128;
        xmA[rb]  = (row & 7) * 16;
    }
    // B fragment addressing
    uint32_t rowB[2], xmB[2];
    uint32_t cbB = ((lid >> 3) & 1) * 16;
#pragma unroll
    for (int p = 0; p < 2; p++) {
        int row = warpN + p * 16 + ((lid >> 4) << 3) + (lid & 7);
        rowB[p] = row * 128;
        xmB[p]  = (row & 7) * 16;
    }

    bool ev = (tig & 1) == 0;
    int Jl_base = (warpN >> 2) + (tig >> 1);
    float c_reg[4][4];
#pragma unroll
    for (int rb = 0; rb < 4; rb++) {
        int rrow = warpM + rb * 16 + g + (ev ? 0 : 8);
#pragma unroll
        for (int nb = 0; nb < 4; nb++) {
            int Jl = Jl_base + 2 * nb;
            c_reg[rb][nb] = c0[(size_t)(bm + rrow) * Hc + jg0 + Jl];
        }
    }
    if (tid < 128) {
        cl_s[tid] = cap_len[bm + tid];
        pb_s[tid] = pb[bn + tid];
    }
    if (tid == 0) {
#pragma unroll
        for (int i = 0; i < 3; i++) MBARRIER_INIT(sb + MB_OFF + i * 8, 1);
    }
    __syncthreads();

    // h-output tile coords for this CTA
    int tsc = bx >> 1;
    int hoff = (bx & 1) * 32;

    auto load_sc = [&](int t, int sc) {           // tid0 only
        int s = sc % 3;
        uint32_t mb = sb + MB_OFF + s * 8;
        MBARRIER_EXPECT_TX(mb, STG);
        const char* asrc = (sc < 8)
            ? (const char*)xt  + ((((size_t)t * 8 + bmT) * 8 + sc) << 14)
            : (const char*)hT  + ((((size_t)(t & 1) * 8 + bmT) * 16 + (sc - 8)) << 14);
        TMA_BULK(sb + SA_OFF + s * STG, asrc, 16384, mb);
        const char* bsrc = (const char*)WpT + (((size_t)bx * 24 + sc) << 14);
        TMA_BULK(sb + SA_OFF + s * STG + 16384, bsrc, 16384, mb);
    };

    for (int t = 0; t < Tc; t++) {
        if (tid == 0) { load_sc(t, 0); load_sc(t, 1); }

        float acc[4][4][4];
#pragma unroll
        for (int i = 0; i < 4; i++)
#pragma unroll
            for (int j = 0; j < 4; j++)
#pragma unroll
                for (int q = 0; q < 4; q++) acc[i][j][q] = 0.f;

        for (int sc = 0; sc < NSC; sc++) {
            if (sc == 6 && tid == 0) {  // before first h-tile load (SC8 issued here)
                unsigned int target = (unsigned int)(NCTA * t);
                unsigned int v;
                do {
                    asm volatile("ld.acquire.gpu.global.u32 %0, [%1];"
                                 : "=r"(v) : "l"(counter) : "memory");
                } while (v < target);
                FENCE_ASYNC();
            }
            MBARRIER_WAIT_PARITY(sb + MB_OFF + (sc % 3) * 8, (sc / 3) & 1);
            __syncthreads();            // stage (sc+2)%3 reads from iter sc-1 complete
            if (tid == 0 && sc + 2 < NSC) load_sc(t, sc + 2);
            uint32_t aB = sb + SA_OFF + (sc % 3) * STG;
            uint32_t bB = aB + 16384;
#pragma unroll
            for (int k16 = 0; k16 < 4; k16++) {
                uint32_t afr[4][4], bfr[2][4];
#pragma unroll
                for (int rb = 0; rb < 4; rb++)
                    ldsm_x4(afr[rb], aB + rowA[rb] + ((cbA + k16 * 32) ^ xmA[rb]));
#pragma unroll
                for (int p = 0; p < 2; p++)
                    ldsm_x4(bfr[p], bB + rowB[p] + ((cbB + k16 * 32) ^ xmB[p]));
#pragma unroll
                for (int rb = 0; rb < 4; rb++) {
                    mma_f16(acc[rb][0], afr[rb], &bfr[0][0]);
                    mma_f16(acc[rb][1], afr[rb], &bfr[0][2]);
                    mma_f16(acc[rb][2], afr[rb], &bfr[1][0]);
                    mma_f16(acc[rb][3], afr[rb], &bfr[1][2]);
                }
            }
        }

        // epilogue: shuffle gates; c in registers; direct swizzled h stores
        char* tb = (char*)hT + ((((size_t)((t + 1) & 1) * 8 + bmT) * 16 + tsc) << 14);
#pragma unroll
        for (int rb = 0; rb < 4; rb++) {
            int r0 = warpM + rb * 16 + g;
            int rrow = ev ? r0 : (r0 + 8);
            int cl = cl_s[rrow];
#pragma unroll
            for (int nb = 0; nb < 4; nb++) {
                float v0 = acc[rb][nb][0], v1 = acc[rb][nb][1];
                float v2 = acc[rb][nb][2], v3 = acc[rb][nb][3];
                float x = ev ? v2 : v0, y = ev ? v3 : v1;
                float px = __shfl_xor_sync(0xffffffffu, x, 1);
                float py = __shfl_xor_sync(0xffffffffu, y, 1);
                float gi = ev ? v0 : px, gf = ev ? v1 : py;
                float gg = ev ? px : v2, go = ev ? py : v3;
                int Jl = Jl_base + 2 * nb;
                float4 pbv = *(const float4*)(pb_s + 4 * Jl);
                float si = fsig(gi + pbv.x);
                float sf = fsig(gf + pbv.y);
                float tg = ftanh(gg + pbv.z);
                float so = fsig(go + pbv.w);
                float cn = sf * c_reg[rb][nb] + si * tg;
                c_reg[rb][nb] = cn;
                __half hv = __float2half_rn(so * ftanh(cn));
                uint32_t off = rrow * 128 + (hoff + Jl) * 2;
                off ^= (off >> 3) & 0x70;
                *(__half*)(tb + off) = hv;
                if (cl - 1 == t) hlast[(size_t)(bm + rrow) * Hc + jg0 + Jl] = hv;
            }
        }
        __syncthreads();                // all h stores done before release
        if (tid == 0) {
            FENCE_ASYNC();              // make generic stores visible to async (TMA) readers
            asm volatile("red.release.gpu.global.add.u32 [%0], %1;"
                         :: "l"(counter), "r"(1u) : "memory");
        }
    }
}

// ---------------- launch ----------------
extern "C" void kernel_launch(void* const* d_in, const int* in_sizes, int n_in,
                              void* d_out, int out_size) {
    const int*   cap     = (const int*)  d_in[0];
    const int*   cap_len = (const int*)  d_in[1];
    const float* feat    = (const float*)d_in[2];
    const float* embed   = (const float*)d_in[3];
    const float* W_ih    = (const float*)d_in[4];
    const float* W_hh    = (const float*)d_in[5];
    const float* b_ih    = (const float*)d_in[6];
    const float* b_hh    = (const float*)d_in[7];
    const float* v_ih0   = (const float*)d_in[8];
    const float* g_ih0   = (const float*)d_in[9];
    const float* b_ih0   = (const float*)d_in[10];
    const float* v_ic0   = (const float*)d_in[11];
    const float* g_ic0   = (const float*)d_in[12];
    const float* b_ic0   = (const float*)d_in[13];
    const float* v_mu    = (const float*)d_in[14];
    const float* g_mu    = (const float*)d_in[15];
    const float* b_mu    = (const float*)d_in[16];
    const float* v_s2    = (const float*)d_in[17];
    const float* g_s2    = (const float*)d_in[18];
    const float* b_s2    = (const float*)d_in[19];
    float* out = (float*)d_out;

    __half *Wcat, *Wocat, *WpT, *xt, *hT, *h0, *hl, *embH, *ftH;
    float *bcat, *bocat, *pb, *c0;
    unsigned int* counter;
    cudaGetSymbolAddress((void**)&Wcat,    g_Wcat);
    cudaGetSymbolAddress((void**)&bcat,    g_bcat);
    cudaGetSymbolAddress((void**)&Wocat,   g_Wocat);
    cudaGetSymbolAddress((void**)&bocat,   g_bocat);
    cudaGetSymbolAddress((void**)&WpT,     g_WpT);
    cudaGetSymbolAddress((void**)&pb,      g_pb);
    cudaGetSymbolAddress((void**)&xt,      g_xt);
    cudaGetSymbolAddress((void**)&hT,      g_hT);
    cudaGetSymbolAddress((void**)&h0,      g_h0);
    cudaGetSymbolAddress((void**)&c0,      g_c0);
    cudaGetSymbolAddress((void**)&hl,      g_hl);
    cudaGetSymbolAddress((void**)&embH,    g_embH);
    cudaGetSymbolAddress((void**)&ftH,     g_ftH);
    cudaGetSymbolAddress((void**)&counter, g_counter);

    cudaFuncSetAttribute(hgemm,        cudaFuncAttributeMaxDynamicSharedMemorySize, SMEM_G);
    cudaFuncSetAttribute(lstm_persist, cudaFuncAttributeMaxDynamicSharedMemorySize, SMEM_P);

    cudaMemsetAsync(counter, 0, sizeof(unsigned int));

    wn_kernel<<<Hc, 256>>>(v_ih0, g_ih0, Wcat,            Ac);
    wn_kernel<<<Hc, 256>>>(v_ic0, g_ic0, Wcat + Hc * Ac,  Ac);
    wn_kernel<<<Lc, 256>>>(v_mu,  g_mu,  Wocat,           Hc);
    wn_kernel<<<Lc, 256>>>(v_s2,  g_s2,  Wocat + Lc * Hc, Hc);
    pack2<<<(2 * Hc + 255) / 256, 256>>>(b_ih0, b_ic0, bcat, Hc);
    pack2<<<(2 * Lc + 255) / 256, 256>>>(b_mu,  b_s2,  bocat, Lc);
    permute_tiled<<<Nw, 256>>>(W_hh, W_ih, b_ih, b_hh, WpT, pb);
    half_copy<<<(Vc * Ec + 255) / 256, 256>>>(embed, embH, Vc * Ec);
    half_copy<<<(Bc * Ac + 255) / 256, 256>>>(feat, ftH, Bc * Ac);

    // gather all embed tiles for all steps (tiled + swizzled)
    gather_xt<<<(Tc * Bc) / 4, 256>>>(embH, cap, xt);

    // init: h0 (fp16 linear) and c0 (fp32), fused N=2048; then repack h0 -> hT[0]
    {
        dim3 grid(2 * Hc / 128, Bc / 128);
        hgemm<<<grid, 256, SMEM_G>>>(ftH, Ac, Ac / 32, Wcat, Ac, bcat,
                                     (float*)h0, Hc, 1, c0, Hc, 0, Hc);
        repack_h0<<<(Bc * Hc / 8) / 256, 256>>>(h0, hT);
    }

    // recurrence: persistent kernel, all tiles via bulk-TMA
    {
        dim3 grid(Nw / 128, Bc / 128);       // (32, 8) = 256 CTAs, 2/SM
        lstm_persist<<<grid, 256, SMEM_P>>>(xt, WpT, pb, c0, hT, hl, cap_len, counter);
    }

    // outputs: mu and sigma2 fused, N=512
    {
        dim3 grid(2 * Lc / 128, Bc / 128);
        hgemm<<<grid, 256, SMEM_G>>>(hl, Hc, Hc / 32, Wocat, Hc, bocat,
                                     out, Lc, 0, out + Bc * Lc, Lc, 0, Lc);
    }
}

// round 16
// speedup vs baseline: 1.5642x; 1.0655x over previous
#include <cuda_runtime.h>
#include <cuda_fp16.h>
#include <cstdint>
#include <math.h>

// ---------------- problem constants ----------------
#define Bc 1024   // batch
#define Tc 40     // timesteps
#define Ec 512    // embed dim
#define Hc 1024   // hidden
#define Lc 256    // latent out
#define Ac 2048   // feature dim
#define Vc 30000  // vocab
#define Nw 4096   // 4*H
#define NCTA 256

// ---------------- device scratch (no allocation) ----------------
__device__ __half g_Wcat [2 * Hc * Ac];
__device__ float  g_bcat [2 * Hc];
__device__ __half g_Wocat[2 * Lc * Hc];
__device__ float  g_bocat[2 * Lc];
__device__ __align__(128) __half g_WpT[Nw * (Hc + Ec)];   // tiled+swizzled weights
__device__ float  g_pb   [Nw];
__device__ __align__(128) __half g_xt [(size_t)Tc * 8 * 8 * 8192];  // gathered embed tiles
__device__ __align__(128) __half g_hT [2 * 8 * 16 * 8192];          // tiled h state
__device__ __half g_h0   [Bc * Hc];
__device__ float  g_c0   [Bc * Hc];
__device__ __half g_hl   [Bc * Hc];
__device__ __half g_embH [Vc * Ec];
__device__ __half g_ftH  [Bc * Ac];
__device__ unsigned int g_counter;

// ---------------- helpers ----------------
__device__ __forceinline__ uint32_t smem_u32(const void* p) {
    uint32_t a;
    asm("{ .reg .u64 t; cvta.to.shared.u64 t, %1; cvt.u32.u64 %0, t; }" : "=r"(a) : "l"(p));
    return a;
}
#define CP_ASYNC16(dst, src) \
    asm volatile("cp.async.cg.shared.global [%0], [%1], 16;" :: "r"(dst), "l"(src))
#define CP_COMMIT() asm volatile("cp.async.commit_group;" ::: "memory")
#define CP_WAIT2()  asm volatile("cp.async.wait_group 2;" ::: "memory")

#define MBARRIER_INIT(addr, cnt) \
    asm volatile("mbarrier.init.shared.b64 [%0], %1;" :: "r"(addr), "r"(cnt) : "memory")
#define MBARRIER_EXPECT_TX(addr, bytes) \
    asm volatile("mbarrier.arrive.expect_tx.shared.b64 _, [%0], %1;" :: "r"(addr), "r"(bytes) : "memory")
#define MBARRIER_WAIT_PARITY(addr, par) do {                                        \
    uint32_t _m = (addr), _p = (par), _d;                                           \
    asm volatile("{ .reg .pred p; mbarrier.try_wait.parity.acquire.cta.shared::cta.b64 p, [%1], %2; selp.b32 %0,1,0,p; }" \
        : "=r"(_d) : "r"(_m), "r"(_p) : "memory");                                  \
    if (!_d) {                                                                      \
        asm volatile("{ .reg .pred P1; WL_%=: mbarrier.try_wait.parity.acquire.cta.shared::cta.b64 P1, [%0], %1, 0x989680; @P1 bra.uni WD_%=; bra.uni WL_%=; WD_%=: }" \
            :: "r"(_m), "r"(_p) : "memory");                                        \
    }                                                                               \
} while (0)
#define TMA_BULK(dst, src, bytes, mbar) \
    asm volatile("cp.async.bulk.shared::cta.global.mbarrier::complete_tx::bytes [%0], [%1], %2, [%3];" \
        :: "r"(dst), "l"(src), "r"(bytes), "r"(mbar) : "memory")
#define FENCE_ASYNC() asm volatile("fence.proxy.async;" ::: "memory")

__device__ __forceinline__ void mma_f16(float* d, const uint32_t* a, const uint32_t* b) {
    asm volatile(
        "mma.sync.aligned.m16n8k16.row.col.f32.f16.f16.f32 "
        "{%0,%1,%2,%3}, {%4,%5,%6,%7}, {%8,%9}, {%0,%1,%2,%3};"
        : "+f"(d[0]), "+f"(d[1]), "+f"(d[2]), "+f"(d[3])
        : "r"(a[0]), "r"(a[1]), "r"(a[2]), "r"(a[3]), "r"(b[0]), "r"(b[1]));
}
__device__ __forceinline__ void ldsm_x4(uint32_t* r, uint32_t addr) {
    asm volatile("ldmatrix.sync.aligned.m8n8.x4.shared.b16 {%0,%1,%2,%3}, [%4];"
        : "=r"(r[0]), "=r"(r[1]), "=r"(r[2]), "=r"(r[3]) : "r"(addr));
}
__device__ __forceinline__ float fex2(float x) { float r; asm("ex2.approx.f32 %0, %1;" : "=f"(r) : "f"(x)); return r; }
__device__ __forceinline__ float frcp(float x) { float r; asm("rcp.approx.f32 %0, %1;" : "=f"(r) : "f"(x)); return r; }
__device__ __forceinline__ float fsig(float x)  { return frcp(1.f + fex2(-1.4426950408889634f * x)); }
__device__ __forceinline__ float ftanh(float x) { return 1.f - 2.f * frcp(1.f + fex2(2.8853900817779268f * x)); }

// ---------------- prep kernels ----------------
__global__ void wn_kernel(const float* __restrict__ v, const float* __restrict__ g,
                          __half* __restrict__ W, int cols) {
    int r = blockIdx.x;
    const float* vr = v + (size_t)r * cols;
    float s = 0.f;
    for (int c = threadIdx.x; c < cols; c += blockDim.x) { float x = vr[c]; s += x * x; }
    __shared__ float sh[32];
    for (int o = 16; o > 0; o >>= 1) s += __shfl_down_sync(0xffffffffu, s, o);
    if ((threadIdx.x & 31) == 0) sh[threadIdx.x >> 5] = s;
    __syncthreads();
    if (threadIdx.x < 32) {
        float t = (threadIdx.x < (blockDim.x >> 5)) ? sh[threadIdx.x] : 0.f;
        for (int o = 16; o > 0; o >>= 1) t += __shfl_down_sync(0xffffffffu, t, o);
        if (threadIdx.x == 0) sh[0] = t;
    }
    __syncthreads();
    float scale = g[r] / sqrtf(sh[0]);
    __half* Wr = W + (size_t)r * cols;
    for (int c = threadIdx.x; c < cols; c += blockDim.x) Wr[c] = __float2half_rn(vr[c] * scale);
}

__global__ void permute_tiled(const float* __restrict__ Whh, const float* __restrict__ Wih,
                              const float* __restrict__ bih, const float* __restrict__ bhh,
                              __half* __restrict__ WpT, float* __restrict__ pb) {
    int n = blockIdx.x;
    int gt = n >> 10, j = n & 1023;
    int np = (j << 2) | gt;
    int bnT = np >> 7, nl = np & 127;
    char* basep = (char*)WpT;
    const float* s1 = Whh + (size_t)n * Hc;
    const float* s2 = Wih + (size_t)n * Ec;
    for (int k = threadIdx.x; k < Hc; k += blockDim.x) {
        int sc = 8 + (k >> 6), c = k & 63;
        size_t tb = ((size_t)(bnT * 24 + sc)) << 14;
        uint32_t off = nl * 128 + c * 2;
        off ^= (off >> 3) & 0x70;
        *(__half*)(basep + tb + off) = __float2half_rn(s1[k]);
    }
    for (int k = threadIdx.x; k < Ec; k += blockDim.x) {
        int sc = k >> 6, c = k & 63;
        size_t tb = ((size_t)(bnT * 24 + sc)) << 14;
        uint32_t off = nl * 128 + c * 2;
        off ^= (off >> 3) & 0x70;
        *(__half*)(basep + tb + off) = __float2half_rn(s2[k]);
    }
    if (threadIdx.x == 0) pb[np] = bih[n] + bhh[n];
}

__global__ void gather_xt(const __half* __restrict__ embH, const int* __restrict__ cap,
                          __half* __restrict__ xt) {
    int blk = blockIdx.x;
    int r4 = threadIdx.x >> 6;
    int thr = threadIdx.x & 63;
    int gr = blk * 4 + r4;
    int t = gr / Bc, b = gr % Bc;
    int tok = cap[(size_t)b * Tc + t];
    int bmT = b >> 7, rowl = b & 127;
    int c0 = thr * 8, sc = c0 >> 6, c = c0 & 63;
    const char* src = (const char*)(embH + (size_t)tok * Ec + c0);
    char* tb = (char*)xt + ((((size_t)t * 8 + bmT) * 8 + sc) << 14);
    uint32_t off = rowl * 128 + c * 2;
    off ^= (off >> 3) & 0x70;
    *(float4*)(tb + off) = *(const float4*)src;
}

__global__ void repack_h0(const __half* __restrict__ h0, __half* __restrict__ hT) {
    int e = (blockIdx.x * 256 + threadIdx.x) * 8;
    int b = e >> 10, col = e & 1023;
    int bmT = b >> 7, rowl = b & 127;
    int sc = col >> 6, c = col & 63;
    char* tb = (char*)hT + ((((size_t)bmT) * 16 + sc) << 14);
    uint32_t off = rowl * 128 + c * 2;
    off ^= (off >> 3) & 0x70;
    *(float4*)(tb + off) = *(const float4*)(h0 + (size_t)b * Hc + col);
}

__global__ void half_copy(const float* __restrict__ src, __half* __restrict__ dst, int n) {
    int i = blockIdx.x * blockDim.x + threadIdx.x;
    if (i < n) dst[i] = __float2half_rn(src[i]);
}

__global__ void pack2(const float* __restrict__ a, const float* __restrict__ b,
                      float* __restrict__ dst, int n) {
    int i = blockIdx.x * blockDim.x + threadIdx.x;
    if (i < n) dst[i] = a[i];
    else if (i < 2 * n) dst[i] = b[i - n];
}

// ---------------- fp16 mma.sync GEMM (init / output projections) — R8-proven ----------------
static constexpr int ST    = 128 * 80;
static constexpr int A_OFF = 1024;
static constexpr int B_OFF = A_OFF + 4 * ST;
static constexpr int SMEM_G = B_OFF + 4 * ST;             // 82944

__global__ __launch_bounds__(256, 2)
void hgemm(const __half* __restrict__ A1, int lda1, int kc1,
           const __half* __restrict__ Bw, int ldb,
           const float* __restrict__ bias,
           float* __restrict__ C1, int ldc1, int half1,
           float* __restrict__ C2, int ldc2, int half2, int ncut)
{
    extern __shared__ __align__(1024) char smem[];
    uint32_t sb = smem_u32(smem);
    int tid = threadIdx.x, wid = tid >> 5, lid = tid & 31;
    int g = lid >> 2, tig = lid & 3;
    int warpM = (wid & 1) * 64, warpN = (wid >> 1) * 32;
    int bm = blockIdx.y * 128, bn = blockIdx.x * 128;
    const int NC = kc1;

    uint32_t offA[4], offB[2];
#pragma unroll
    for (int rb = 0; rb < 4; rb++)
        offA[rb] = (warpM + rb * 16 + (lid & 15)) * 80 + (lid >> 4) * 16;
#pragma unroll
    for (int p = 0; p < 2; p++)
        offB[p] = (warpN + p * 16 + ((lid >> 4) << 3) + (lid & 7)) * 80 + ((lid >> 3) & 1) * 16;

    float acc[4][4][4];
#pragma unroll
    for (int i = 0; i < 4; i++)
#pragma unroll
        for (int j = 0; j < 4; j++)
#pragma unroll
            for (int q = 0; q < 4; q++) acc[i][j][q] = 0.f;

    auto load_chunk = [&](int c, int s) {
        uint32_t aB = sb + A_OFF + s * ST;
        uint32_t bB = sb + B_OFF + s * ST;
#pragma unroll
        for (int i = 0; i < 2; i++) {
            int seg = tid + i * 256;
            int m = seg >> 2, sg = seg & 3;
            CP_ASYNC16(aB + m * 80 + sg * 16, A1 + (size_t)(bm + m) * lda1 + c * 32 + sg * 8);
        }
#pragma unroll
        for (int i = 0; i < 2; i++) {
            int seg = tid + i * 256;
            int n = seg >> 2, sg = seg & 3;
            CP_ASYNC16(bB + n * 80 + sg * 16, Bw + (size_t)(bn + n) * ldb + c * 32 + sg * 8);
        }
    };

    for (int p = 0; p < 3; p++) { load_chunk(p, p); CP_COMMIT(); }

    for (int c = 0; c < NC; c++) {
        int s = c & 3;
        CP_WAIT2();
        __syncthreads();
        if (c + 3 < NC) load_chunk(c + 3, (c + 3) & 3);
        CP_COMMIT();
        uint32_t aB = sb + A_OFF + s * ST;
        uint32_t bB = sb + B_OFF + s * ST;
#pragma unroll
        for (int k16 = 0; k16 < 2; k16++) {
            uint32_t afr[4][4], bfr[2][4];
#pragma unroll
            for (int rb = 0; rb < 4; rb++) ldsm_x4(afr[rb], aB + offA[rb] + k16 * 32);
#pragma unroll
            for (int p = 0; p < 2; p++) ldsm_x4(bfr[p], bB + offB[p] + k16 * 32);
#pragma unroll
            for (int rb = 0; rb < 4; rb++) {
                mma_f16(acc[rb][0], afr[rb], &bfr[0][0]);
                mma_f16(acc[rb][1], afr[rb], &bfr[0][2]);
                mma_f16(acc[rb][2], afr[rb], &bfr[1][0]);
                mma_f16(acc[rb][3], afr[rb], &bfr[1][2]);
            }
        }
    }

    float* Cd; int cb, ldc, hf;
    if (bn < ncut) { Cd = C1; cb = bn;        ldc = ldc1; hf = half1; }
    else           { Cd = C2; cb = bn - ncut; ldc = ldc2; hf = half2; }
#pragma unroll
    for (int rb = 0; rb < 4; rb++) {
#pragma unroll
        for (int nb = 0; nb < 4; nb++) {
            int coll = warpN + nb * 8 + 2 * tig;
            int col = cb + coll;
            int r0 = bm + warpM + rb * 16 + g;
            float b0 = bias[bn + coll], b1 = bias[bn + coll + 1];
            float v0 = acc[rb][nb][0] + b0, v1 = acc[rb][nb][1] + b1;
            float v2 = acc[rb][nb][2] + b0, v3 = acc[rb][nb][3] + b1;
            if (hf) {
                __half* Ch = (__half*)Cd;
                *(__half2*)(Ch + (size_t)r0 * ldc + col)       = __floats2half2_rn(v0, v1);
                *(__half2*)(Ch + (size_t)(r0 + 8) * ldc + col) = __floats2half2_rn(v2, v3);
            } else {
                *(float2*)(Cd + (size_t)r0 * ldc + col)       = make_float2(v0, v1);
                *(float2*)(Cd + (size_t)(r0 + 8) * ldc + col) = make_float2(v2, v3);
            }
        }
    }
}

// ---------------- persistent LSTM: all-TMA, continuous cross-step pipeline ----------------
// smem: [0,512) pb_s, [512,1024) cl_s, [1024,1048) mbar[3], [2048, +3*32768) stages,
//       [100352, +10240) hsm staging (dedicated — stages stay live across epilogue).
static constexpr int STG    = 32768;                      // 16KB A + 16KB B
static constexpr int MB_OFF = 1024;
static constexpr int SA_OFF = 2048;
static constexpr int HS_OFF = SA_OFF + 3 * STG;           // 100352
static constexpr int SMEM_P = HS_OFF + 10240;             // 110592
#define NSC 24
#define TOTC (Tc * NSC)

__global__ __launch_bounds__(256, 2)
void lstm_persist(const __half* __restrict__ xt,
                  const __half* __restrict__ WpT,
                  const float* __restrict__ pb,
                  const float* __restrict__ c0,
                  __half* __restrict__ hT,
                  __half* __restrict__ hlast,
                  const int* __restrict__ cap_len,
                  unsigned int* __restrict__ counter)
{
    extern __shared__ __align__(1024) char smem[];
    uint32_t sb = smem_u32(smem);
    int tid = threadIdx.x, wid = tid >> 5, lid = tid & 31;
    int g = lid >> 2, tig = lid & 3;
    int warpM = (wid & 1) * 64, warpN = (wid >> 1) * 32;
    int bx = blockIdx.x, bmT = blockIdx.y;
    int bn = bx * 128, bm = bmT * 128;
    int jg0 = bn >> 2;
    float*  pb_s = (float*)smem;
    int*    cl_s = (int*)(smem + 512);
    __half* hsm  = (__half*)(smem + HS_OFF);   // pitch 40 halves (80B)

    uint32_t rowA[4], xmA[4];
    uint32_t cbA = (lid >> 4) * 16;
#pragma unroll
    for (int rb = 0; rb < 4; rb++) {
        int row = warpM + rb * 16 + (lid & 15);
        rowA[rb] = row * 128;
        xmA[rb]  = (row & 7) * 16;
    }
    uint32_t rowB[2], xmB[2];
    uint32_t cbB = ((lid >> 3) & 1) * 16;
#pragma unroll
    for (int p = 0; p < 2; p++) {
        int row = warpN + p * 16 + ((lid >> 4) << 3) + (lid & 7);
        rowB[p] = row * 128;
        xmB[p]  = (row & 7) * 16;
    }

    bool ev = (tig & 1) == 0;
    int Jl_base = (warpN >> 2) + (tig >> 1);
    float c_reg[4][4];
#pragma unroll
    for (int rb = 0; rb < 4; rb++) {
        int rrow = warpM + rb * 16 + g + (ev ? 0 : 8);
#pragma unroll
        for (int nb = 0; nb < 4; nb++) {
            int Jl = Jl_base + 2 * nb;
            c_reg[rb][nb] = c0[(size_t)(bm + rrow) * Hc + jg0 + Jl];
        }
    }
    if (tid < 128) {
        cl_s[tid] = cap_len[bm + tid];
        pb_s[tid] = pb[bn + tid];
    }
    if (tid == 0) {
#pragma unroll
        for (int i = 0; i < 3; i++) MBARRIER_INIT(sb + MB_OFF + i * 8, 1);
    }
    __syncthreads();

    int tsc = bx >> 1;
    int hoff = (bx & 1) * 32;

    auto load_gc = [&](int gc) {                  // tid0 only
        int t2 = gc / NSC, sc2 = gc % NSC;
        int s = gc % 3;
        uint32_t mb = sb + MB_OFF + s * 8;
        MBARRIER_EXPECT_TX(mb, STG);
        const char* asrc = (sc2 < 8)
            ? (const char*)xt + ((((size_t)t2 * 8 + bmT) * 8 + sc2) << 14)
            : (const char*)hT + ((((size_t)(t2 & 1) * 8 + bmT) * 16 + (sc2 - 8)) << 14);
        TMA_BULK(sb + SA_OFF + s * STG, asrc, 16384, mb);
        const char* bsrc = (const char*)WpT + (((size_t)bx * 24 + sc2) << 14);
        TMA_BULK(sb + SA_OFF + s * STG + 16384, bsrc, 16384, mb);
    };

    if (tid == 0) { load_gc(0); load_gc(1); }     // one-time prologue

    for (int t = 0; t < Tc; t++) {
        float acc[4][4][4];
#pragma unroll
        for (int i = 0; i < 4; i++)
#pragma unroll
            for (int j = 0; j < 4; j++)
#pragma unroll
                for (int q = 0; q < 4; q++) acc[i][j][q] = 0.f;

        for (int sc = 0; sc < NSC; sc++) {
            int gc = t * NSC + sc;
            if (sc == 6 && tid == 0) {            // gate h-loads of step t (issued as gc+2)
                unsigned int target = (unsigned int)(NCTA * t);
                unsigned int v;
                do {
                    asm volatile("ld.acquire.gpu.global.u32 %0, [%1];"
                                 : "=r"(v) : "l"(counter) : "memory");
                } while (v < target);
                FENCE_ASYNC();
            }
            MBARRIER_WAIT_PARITY(sb + MB_OFF + (gc % 3) * 8, (sc / 3) & 1);
            __syncthreads();                      // readers of stage (gc+2)%3 done (iter gc-1)
            if (tid == 0 && gc + 2 < TOTC) load_gc(gc + 2);
            uint32_t aB = sb + SA_OFF + (gc % 3) * STG;
            uint32_t bB = aB + 16384;
#pragma unroll
            for (int k16 = 0; k16 < 4; k16++) {
                uint32_t afr[4][4], bfr[2][4];
#pragma unroll
                for (int rb = 0; rb < 4; rb++)
                    ldsm_x4(afr[rb], aB + rowA[rb] + ((cbA + k16 * 32) ^ xmA[rb]));
#pragma unroll
                for (int p = 0; p < 2; p++)
                    ldsm_x4(bfr[p], bB + rowB[p] + ((cbB + k16 * 32) ^ xmB[p]));
#pragma unroll
                for (int rb = 0; rb < 4; rb++) {
                    mma_f16(acc[rb][0], afr[rb], &bfr[0][0]);
                    mma_f16(acc[rb][1], afr[rb], &bfr[0][2]);
                    mma_f16(acc[rb][2], afr[rb], &bfr[1][0]);
                    mma_f16(acc[rb][3], afr[rb], &bfr[1][2]);
                }
            }
        }

        // epilogue: shuffle gates -> hsm staging (dedicated; stages keep receiving TMA)
#pragma unroll
        for (int rb = 0; rb < 4; rb++) {
            int r0 = warpM + rb * 16 + g;
            int rrow = ev ? r0 : (r0 + 8);
#pragma unroll
            for (int nb = 0; nb < 4; nb++) {
                float v0 = acc[rb][nb][0], v1 = acc[rb][nb][1];
                float v2 = acc[rb][nb][2], v3 = acc[rb][nb][3];
                float x = ev ? v2 : v0, y = ev ? v3 : v1;
                float px = __shfl_xor_sync(0xffffffffu, x, 1);
                float py = __shfl_xor_sync(0xffffffffu, y, 1);
                float gi = ev ? v0 : px, gf = ev ? v1 : py;
                float gg = ev ? px : v2, go = ev ? py : v3;
                int Jl = Jl_base + 2 * nb;
                float4 pbv = *(const float4*)(pb_s + 4 * Jl);
                float si = fsig(gi + pbv.x);
                float sf = fsig(gf + pbv.y);
                float tg = ftanh(gg + pbv.z);
                float so = fsig(go + pbv.w);
                float cn = sf * c_reg[rb][nb] + si * tg;
                c_reg[rb][nb] = cn;
                hsm[rrow * 40 + Jl] = __float2half_rn(so * ftanh(cn));
            }
        }
        __syncthreads();
        // coalesced float4 stores: 512 chunks of 8 cols
        {
            char* tb = (char*)hT + ((((size_t)((t + 1) & 1) * 8 + bmT) * 16 + tsc) << 14);
            for (int idx = tid; idx < 512; idx += 256) {
                int row = idx >> 2, ch = idx & 3;
                int jl0 = ch * 8;
                float4 val = *(const float4*)(hsm + row * 40 + jl0);
                uint32_t off = row * 128 + (hoff + jl0) * 2;
                off ^= (off >> 3) & 0x70;
                *(float4*)(tb + off) = val;
                if (cl_s[row] - 1 == t)
                    *(float4*)(hlast + (size_t)(bm + row) * Hc + jg0 + jl0) = val;
            }
        }
        __syncthreads();
        if (tid == 0) {
            FENCE_ASYNC();
            asm volatile("red.release.gpu.global.add.u32 [%0], %1;"
                         :: "l"(counter), "r"(1u) : "memory");
        }
    }
}

// ---------------- launch ----------------
extern "C" void kernel_launch(void* const* d_in, const int* in_sizes, int n_in,
                              void* d_out, int out_size) {
    const int*   cap     = (const int*)  d_in[0];
    const int*   cap_len = (const int*)  d_in[1];
    const float* feat    = (const float*)d_in[2];
    const float* embed   = (const float*)d_in[3];
    const float* W_ih    = (const float*)d_in[4];
    const float* W_hh    = (const float*)d_in[5];
    const float* b_ih    = (const float*)d_in[6];
    const float* b_hh    = (const float*)d_in[7];
    const float* v_ih0   = (const float*)d_in[8];
    const float* g_ih0   = (const float*)d_in[9];
    const float* b_ih0   = (const float*)d_in[10];
    const float* v_ic0   = (const float*)d_in[11];
    const float* g_ic0   = (const float*)d_in[12];
    const float* b_ic0   = (const float*)d_in[13];
    const float* v_mu    = (const float*)d_in[14];
    const float* g_mu    = (const float*)d_in[15];
    const float* b_mu    = (const float*)d_in[16];
    const float* v_s2    = (const float*)d_in[17];
    const float* g_s2    = (const float*)d_in[18];
    const float* b_s2    = (const float*)d_in[19];
    float* out = (float*)d_out;

    __half *Wcat, *Wocat, *WpT, *xt, *hT, *h0, *hl, *embH, *ftH;
    float *bcat, *bocat, *pb, *c0;
    unsigned int* counter;
    cudaGetSymbolAddress((void**)&Wcat,    g_Wcat);
    cudaGetSymbolAddress((void**)&bcat,    g_bcat);
    cudaGetSymbolAddress((void**)&Wocat,   g_Wocat);
    cudaGetSymbolAddress((void**)&bocat,   g_bocat);
    cudaGetSymbolAddress((void**)&WpT,     g_WpT);
    cudaGetSymbolAddress((void**)&pb,      g_pb);
    cudaGetSymbolAddress((void**)&xt,      g_xt);
    cudaGetSymbolAddress((void**)&hT,      g_hT);
    cudaGetSymbolAddress((void**)&h0,      g_h0);
    cudaGetSymbolAddress((void**)&c0,      g_c0);
    cudaGetSymbolAddress((void**)&hl,      g_hl);
    cudaGetSymbolAddress((void**)&embH,    g_embH);
    cudaGetSymbolAddress((void**)&ftH,     g_ftH);
    cudaGetSymbolAddress((void**)&counter, g_counter);

    cudaFuncSetAttribute(hgemm,        cudaFuncAttributeMaxDynamicSharedMemorySize, SMEM_G);
    cudaFuncSetAttribute(lstm_persist, cudaFuncAttributeMaxDynamicSharedMemorySize, SMEM_P);

    cudaMemsetAsync(counter, 0, sizeof(unsigned int));

    wn_kernel<<<Hc, 256>>>(v_ih0, g_ih0, Wcat,            Ac);
    wn_kernel<<<Hc, 256>>>(v_ic0, g_ic0, Wcat + Hc * Ac,  Ac);
    wn_kernel<<<Lc, 256>>>(v_mu,  g_mu,  Wocat,           Hc);
    wn_kernel<<<Lc, 256>>>(v_s2,  g_s2,  Wocat + Lc * Hc, Hc);
    pack2<<<(2 * Hc + 255) / 256, 256>>>(b_ih0, b_ic0, bcat, Hc);
    pack2<<<(2 * Lc + 255) / 256, 256>>>(b_mu,  b_s2,  bocat, Lc);
    permute_tiled<<<Nw, 256>>>(W_hh, W_ih, b_ih, b_hh, WpT, pb);
    half_copy<<<(Vc * Ec + 255) / 256, 256>>>(embed, embH, Vc * Ec);
    half_copy<<<(Bc * Ac + 255) / 256, 256>>>(feat, ftH, Bc * Ac);

    // gather all embed tiles for all steps (tiled + swizzled)
    gather_xt<<<(Tc * Bc) / 4, 256>>>(embH, cap, xt);

    // init: h0 (fp16 linear) and c0 (fp32), fused N=2048; repack h0 -> hT[0]
    {
        dim3 grid(2 * Hc / 128, Bc / 128);
        hgemm<<<grid, 256, SMEM_G>>>(ftH, Ac, Ac / 32, Wcat, Ac, bcat,
                                     (float*)h0, Hc, 1, c0, Hc, 0, Hc);
        repack_h0<<<(Bc * Hc / 8) / 256, 256>>>(h0, hT);
    }

    // recurrence: persistent kernel, all-TMA, continuous pipeline
    {
        dim3 grid(Nw / 128, Bc / 128);       // (32, 8) = 256 CTAs, 2/SM
        lstm_persist<<<grid, 256, SMEM_P>>>(xt, WpT, pb, c0, hT, hl, cap_len, counter);
    }

    // outputs: mu and sigma2 fused, N=512
    {
        dim3 grid(2 * Lc / 128, Bc / 128);
        hgemm<<<grid, 256, SMEM_G>>>(hl, Hc, Hc / 32, Wocat, Hc, bocat,
                                     out, Lc, 0, out + Bc * Lc, Lc, 0, Lc);
    }
}

// round 17
// speedup vs baseline: 1.6234x; 1.0378x over previous
#include <cuda_runtime.h>
#include <cuda_fp16.h>
#include <cstdint>
#include <math.h>

// ---------------- problem constants ----------------
#define Bc 1024   // batch
#define Tc 40     // timesteps
#define Ec 512    // embed dim
#define Hc 1024   // hidden
#define Lc 256    // latent out
#define Ac 2048   // feature dim
#define Vc 30000  // vocab
#define Nw 4096   // 4*H
#define NCTA 256

// ---------------- device scratch (no allocation) ----------------
__device__ __half g_Wcat [2 * Hc * Ac];
__device__ float  g_bcat [2 * Hc];
__device__ __half g_Wocat[2 * Lc * Hc];
__device__ float  g_bocat[2 * Lc];
__device__ __align__(128) __half g_WpT[Nw * (Hc + Ec)];   // tiled+swizzled weights
__device__ float  g_pb   [Nw];
__device__ __align__(128) __half g_xt [(size_t)Tc * 8 * 8 * 8192];  // gathered embed tiles
__device__ __align__(128) __half g_hT [2 * 8 * 16 * 8192];          // tiled h state
__device__ __half g_h0   [Bc * Hc];
__device__ float  g_c0   [Bc * Hc];
__device__ __half g_hl   [Bc * Hc];
__device__ __half g_ftH  [Bc * Ac];
__device__ unsigned int g_counter;

// ---------------- helpers ----------------
__device__ __forceinline__ uint32_t smem_u32(const void* p) {
    uint32_t a;
    asm("{ .reg .u64 t; cvta.to.shared.u64 t, %1; cvt.u32.u64 %0, t; }" : "=r"(a) : "l"(p));
    return a;
}
#define CP_ASYNC16(dst, src) \
    asm volatile("cp.async.cg.shared.global [%0], [%1], 16;" :: "r"(dst), "l"(src))
#define CP_COMMIT() asm volatile("cp.async.commit_group;" ::: "memory")
#define CP_WAIT2()  asm volatile("cp.async.wait_group 2;" ::: "memory")

#define MBARRIER_INIT(addr, cnt) \
    asm volatile("mbarrier.init.shared.b64 [%0], %1;" :: "r"(addr), "r"(cnt) : "memory")
#define MBARRIER_EXPECT_TX(addr, bytes) \
    asm volatile("mbarrier.arrive.expect_tx.shared.b64 _, [%0], %1;" :: "r"(addr), "r"(bytes) : "memory")
#define MBARRIER_WAIT_PARITY(addr, par) do {                                        \
    uint32_t _m = (addr), _p = (par), _d;                                           \
    asm volatile("{ .reg .pred p; mbarrier.try_wait.parity.acquire.cta.shared::cta.b64 p, [%1], %2; selp.b32 %0,1,0,p; }" \
        : "=r"(_d) : "r"(_m), "r"(_p) : "memory");                                  \
    if (!_d) {                                                                      \
        asm volatile("{ .reg .pred P1; WL_%=: mbarrier.try_wait.parity.acquire.cta.shared::cta.b64 P1, [%0], %1, 0x989680; @P1 bra.uni WD_%=; bra.uni WL_%=; WD_%=: }" \
            :: "r"(_m), "r"(_p) : "memory");                                        \
    }                                                                               \
} while (0)
#define TMA_BULK(dst, src, bytes, mbar) \
    asm volatile("cp.async.bulk.shared::cta.global.mbarrier::complete_tx::bytes [%0], [%1], %2, [%3];" \
        :: "r"(dst), "l"(src), "r"(bytes), "r"(mbar) : "memory")
#define FENCE_ASYNC() asm volatile("fence.proxy.async;" ::: "memory")

__device__ __forceinline__ void mma_f16(float* d, const uint32_t* a, const uint32_t* b) {
    asm volatile(
        "mma.sync.aligned.m16n8k16.row.col.f32.f16.f16.f32 "
        "{%0,%1,%2,%3}, {%4,%5,%6,%7}, {%8,%9}, {%0,%1,%2,%3};"
        : "+f"(d[0]), "+f"(d[1]), "+f"(d[2]), "+f"(d[3])
        : "r"(a[0]), "r"(a[1]), "r"(a[2]), "r"(a[3]), "r"(b[0]), "r"(b[1]));
}
__device__ __forceinline__ void ldsm_x4(uint32_t* r, uint32_t addr) {
    asm volatile("ldmatrix.sync.aligned.m8n8.x4.shared.b16 {%0,%1,%2,%3}, [%4];"
        : "=r"(r[0]), "=r"(r[1]), "=r"(r[2]), "=r"(r[3]) : "r"(addr));
}
__device__ __forceinline__ float fex2(float x) { float r; asm("ex2.approx.f32 %0, %1;" : "=f"(r) : "f"(x)); return r; }
__device__ __forceinline__ float frcp(float x) { float r; asm("rcp.approx.f32 %0, %1;" : "=f"(r) : "f"(x)); return r; }
__device__ __forceinline__ float fsig(float x)  { return frcp(1.f + fex2(-1.4426950408889634f * x)); }
__device__ __forceinline__ float ftanh(float x) { return 1.f - 2.f * frcp(1.f + fex2(2.8853900817779268f * x)); }

// ---------------- prep kernels ----------------
// all four weight-norm projections in ONE launch
__global__ void wn_all(const float* __restrict__ v_ih0, const float* __restrict__ g_ih0,
                       const float* __restrict__ v_ic0, const float* __restrict__ g_ic0,
                       const float* __restrict__ v_mu,  const float* __restrict__ g_mu,
                       const float* __restrict__ v_s2,  const float* __restrict__ g_s2,
                       __half* __restrict__ Wcat, __half* __restrict__ Wocat) {
    int r = blockIdx.x;
    const float *v, *gg; __half* W; int cols, lr;
    if (r < Hc)            { v = v_ih0; gg = g_ih0; W = Wcat;                lr = r;            cols = Ac; }
    else if (r < 2 * Hc)   { v = v_ic0; gg = g_ic0; W = Wcat + Hc * Ac;      lr = r - Hc;       cols = Ac; }
    else if (r < 2*Hc+Lc)  { v = v_mu;  gg = g_mu;  W = Wocat;               lr = r - 2 * Hc;   cols = Hc; }
    else                   { v = v_s2;  gg = g_s2;  W = Wocat + Lc * Hc;     lr = r - 2*Hc-Lc;  cols = Hc; }
    const float* vr = v + (size_t)lr * cols;
    float s = 0.f;
    for (int c = threadIdx.x; c < cols; c += blockDim.x) { float x = vr[c]; s += x * x; }
    __shared__ float sh[32];
    for (int o = 16; o > 0; o >>= 1) s += __shfl_down_sync(0xffffffffu, s, o);
    if ((threadIdx.x & 31) == 0) sh[threadIdx.x >> 5] = s;
    __syncthreads();
    if (threadIdx.x < 32) {
        float t = (threadIdx.x < (blockDim.x >> 5)) ? sh[threadIdx.x] : 0.f;
        for (int o = 16; o > 0; o >>= 1) t += __shfl_down_sync(0xffffffffu, t, o);
        if (threadIdx.x == 0) sh[0] = t;
    }
    __syncthreads();
    float scale = gg[lr] / sqrtf(sh[0]);
    __half* Wr = W + (size_t)lr * cols;
    for (int c = threadIdx.x; c < cols; c += blockDim.x) Wr[c] = __float2half_rn(vr[c] * scale);
}

// vectorized tiled+swizzled weight pack: float4 stores (swizzle preserves 16B chunks per row)
__global__ void permute_tiled(const float* __restrict__ Whh, const float* __restrict__ Wih,
                              const float* __restrict__ bih, const float* __restrict__ bhh,
                              __half* __restrict__ WpT, float* __restrict__ pb) {
    int n = blockIdx.x;
    int gt = n >> 10, j = n & 1023;
    int np = (j << 2) | gt;
    int bnT = np >> 7, nl = np & 127;
    uint32_t xmask = (nl & 7) << 4;
    char* basep = (char*)WpT;
    const float* s1 = Whh + (size_t)n * Hc;
    const float* s2 = Wih + (size_t)n * Ec;
    for (int k0 = threadIdx.x * 8; k0 < Hc; k0 += blockDim.x * 8) {
        int sc = 8 + (k0 >> 6), c = k0 & 63;
        size_t tb = ((size_t)(bnT * 24 + sc)) << 14;
        float4 a = *(const float4*)(s1 + k0);
        float4 b = *(const float4*)(s1 + k0 + 4);
        __half h[8] = { __float2half_rn(a.x), __float2half_rn(a.y), __float2half_rn(a.z), __float2half_rn(a.w),
                        __float2half_rn(b.x), __float2half_rn(b.y), __float2half_rn(b.z), __float2half_rn(b.w) };
        *(float4*)(basep + tb + nl * 128 + ((c * 2) ^ xmask)) = *(float4*)h;
    }
    for (int k0 = threadIdx.x * 8; k0 < Ec; k0 += blockDim.x * 8) {
        int sc = k0 >> 6, c = k0 & 63;
        size_t tb = ((size_t)(bnT * 24 + sc)) << 14;
        float4 a = *(const float4*)(s2 + k0);
        float4 b = *(const float4*)(s2 + k0 + 4);
        __half h[8] = { __float2half_rn(a.x), __float2half_rn(a.y), __float2half_rn(a.z), __float2half_rn(a.w),
                        __float2half_rn(b.x), __float2half_rn(b.y), __float2half_rn(b.z), __float2half_rn(b.w) };
        *(float4*)(basep + tb + nl * 128 + ((c * 2) ^ xmask)) = *(float4*)h;
    }
    if (threadIdx.x == 0) pb[np] = bih[n] + bhh[n];
}

// gather embeddings DIRECTLY from fp32 table into tiled+swizzled per-step tiles
__global__ void gather_xt(const float* __restrict__ embed, const int* __restrict__ cap,
                          __half* __restrict__ xt) {
    int blk = blockIdx.x;
    int r4 = threadIdx.x >> 6;
    int thr = threadIdx.x & 63;
    int gr = blk * 4 + r4;
    int t = gr / Bc, b = gr % Bc;
    int tok = cap[(size_t)b * Tc + t];
    int bmT = b >> 7, rowl = b & 127;
    int c0 = thr * 8, sc = c0 >> 6, c = c0 & 63;
    float4 a = *(const float4*)(embed + (size_t)tok * Ec + c0);
    float4 bb = *(const float4*)(embed + (size_t)tok * Ec + c0 + 4);
    __half h[8] = { __float2half_rn(a.x), __float2half_rn(a.y), __float2half_rn(a.z), __float2half_rn(a.w),
                    __float2half_rn(bb.x), __float2half_rn(bb.y), __float2half_rn(bb.z), __float2half_rn(bb.w) };
    char* tb = (char*)xt + ((((size_t)t * 8 + bmT) * 8 + sc) << 14);
    uint32_t off = rowl * 128 + c * 2;
    off ^= (off >> 3) & 0x70;
    *(float4*)(tb + off) = *(float4*)h;
}

__global__ void repack_h0(const __half* __restrict__ h0, __half* __restrict__ hT) {
    int e = (blockIdx.x * 256 + threadIdx.x) * 8;
    int b = e >> 10, col = e & 1023;
    int bmT = b >> 7, rowl = b & 127;
    int sc = col >> 6, c = col & 63;
    char* tb = (char*)hT + ((((size_t)bmT) * 16 + sc) << 14);
    uint32_t off = rowl * 128 + c * 2;
    off ^= (off >> 3) & 0x70;
    *(float4*)(tb + off) = *(const float4*)(h0 + (size_t)b * Hc + col);
}

__global__ void half_copy(const float* __restrict__ src, __half* __restrict__ dst, int n) {
    int i = blockIdx.x * blockDim.x + threadIdx.x;
    if (i < n) dst[i] = __float2half_rn(src[i]);
}

// fused bias packs: [0,2Hc) -> bcat, [2Hc, 2Hc+2Lc) -> bocat
__global__ void pack_bias(const float* __restrict__ b_ih0, const float* __restrict__ b_ic0,
                          const float* __restrict__ b_mu,  const float* __restrict__ b_s2,
                          float* __restrict__ bcat, float* __restrict__ bocat) {
    int i = blockIdx.x * blockDim.x + threadIdx.x;
    if (i < Hc) bcat[i] = b_ih0[i];
    else if (i < 2 * Hc) bcat[i] = b_ic0[i - Hc];
    else if (i < 2 * Hc + Lc) bocat[i - 2 * Hc] = b_mu[i - 2 * Hc];
    else if (i < 2 * Hc + 2 * Lc) bocat[i - 2 * Hc] = b_s2[i - 2 * Hc - Lc];
}

// ---------------- fp16 mma.sync GEMM (init / output projections) — R8-proven ----------------
static constexpr int ST    = 128 * 80;
static constexpr int A_OFF = 1024;
static constexpr int B_OFF = A_OFF + 4 * ST;
static constexpr int SMEM_G = B_OFF + 4 * ST;             // 82944

__global__ __launch_bounds__(256, 2)
void hgemm(const __half* __restrict__ A1, int lda1, int kc1,
           const __half* __restrict__ Bw, int ldb,
           const float* __restrict__ bias,
           float* __restrict__ C1, int ldc1, int half1,
           float* __restrict__ C2, int ldc2, int half2, int ncut)
{
    extern __shared__ __align__(1024) char smem[];
    uint32_t sb = smem_u32(smem);
    int tid = threadIdx.x, wid = tid >> 5, lid = tid & 31;
    int g = lid >> 2, tig = lid & 3;
    int warpM = (wid & 1) * 64, warpN = (wid >> 1) * 32;
    int bm = blockIdx.y * 128, bn = blockIdx.x * 128;
    const int NC = kc1;

    uint32_t offA[4], offB[2];
#pragma unroll
    for (int rb = 0; rb < 4; rb++)
        offA[rb] = (warpM + rb * 16 + (lid & 15)) * 80 + (lid >> 4) * 16;
#pragma unroll
    for (int p = 0; p < 2; p++)
        offB[p] = (warpN + p * 16 + ((lid >> 4) << 3) + (lid & 7)) * 80 + ((lid >> 3) & 1) * 16;

    float acc[4][4][4];
#pragma unroll
    for (int i = 0; i < 4; i++)
#pragma unroll
        for (int j = 0; j < 4; j++)
#pragma unroll
            for (int q = 0; q < 4; q++) acc[i][j][q] = 0.f;

    auto load_chunk = [&](int c, int s) {
        uint32_t aB = sb + A_OFF + s * ST;
        uint32_t bB = sb + B_OFF + s * ST;
#pragma unroll
        for (int i = 0; i < 2; i++) {
            int seg = tid + i * 256;
            int m = seg >> 2, sg = seg & 3;
            CP_ASYNC16(aB + m * 80 + sg * 16, A1 + (size_t)(bm + m) * lda1 + c * 32 + sg * 8);
        }
#pragma unroll
        for (int i = 0; i < 2; i++) {
            int seg = tid + i * 256;
            int n = seg >> 2, sg = seg & 3;
            CP_ASYNC16(bB + n * 80 + sg * 16, Bw + (size_t)(bn + n) * ldb + c * 32 + sg * 8);
        }
    };

    for (int p = 0; p < 3; p++) { load_chunk(p, p); CP_COMMIT(); }

    for (int c = 0; c < NC; c++) {
        int s = c & 3;
        CP_WAIT2();
        __syncthreads();
        if (c + 3 < NC) load_chunk(c + 3, (c + 3) & 3);
        CP_COMMIT();
        uint32_t aB = sb + A_OFF + s * ST;
        uint32_t bB = sb + B_OFF + s * ST;
#pragma unroll
        for (int k16 = 0; k16 < 2; k16++) {
            uint32_t afr[4][4], bfr[2][4];
#pragma unroll
            for (int rb = 0; rb < 4; rb++) ldsm_x4(afr[rb], aB + offA[rb] + k16 * 32);
#pragma unroll
            for (int p = 0; p < 2; p++) ldsm_x4(bfr[p], bB + offB[p] + k16 * 32);
#pragma unroll
            for (int rb = 0; rb < 4; rb++) {
                mma_f16(acc[rb][0], afr[rb], &bfr[0][0]);
                mma_f16(acc[rb][1], afr[rb], &bfr[0][2]);
                mma_f16(acc[rb][2], afr[rb], &bfr[1][0]);
                mma_f16(acc[rb][3], afr[rb], &bfr[1][2]);
            }
        }
    }

    float* Cd; int cb, ldc, hf;
    if (bn < ncut) { Cd = C1; cb = bn;        ldc = ldc1; hf = half1; }
    else           { Cd = C2; cb = bn - ncut; ldc = ldc2; hf = half2; }
#pragma unroll
    for (int rb = 0; rb < 4; rb++) {
#pragma unroll
        for (int nb = 0; nb < 4; nb++) {
            int coll = warpN + nb * 8 + 2 * tig;
            int col = cb + coll;
            int r0 = bm + warpM + rb * 16 + g;
            float b0 = bias[bn + coll], b1 = bias[bn + coll + 1];
            float v0 = acc[rb][nb][0] + b0, v1 = acc[rb][nb][1] + b1;
            float v2 = acc[rb][nb][2] + b0, v3 = acc[rb][nb][3] + b1;
            if (hf) {
                __half* Ch = (__half*)Cd;
                *(__half2*)(Ch + (size_t)r0 * ldc + col)       = __floats2half2_rn(v0, v1);
                *(__half2*)(Ch + (size_t)(r0 + 8) * ldc + col) = __floats2half2_rn(v2, v3);
            } else {
                *(float2*)(Cd + (size_t)r0 * ldc + col)       = make_float2(v0, v1);
                *(float2*)(Cd + (size_t)(r0 + 8) * ldc + col) = make_float2(v2, v3);
            }
        }
    }
}

// ---------------- persistent LSTM: all-TMA, continuous cross-step pipeline (R16-proven) ----------------
static constexpr int STG    = 32768;                      // 16KB A + 16KB B
static constexpr int MB_OFF = 1024;
static constexpr int SA_OFF = 2048;
static constexpr int HS_OFF = SA_OFF + 3 * STG;           // 100352
static constexpr int SMEM_P = HS_OFF + 10240;             // 110592
#define NSC 24
#define TOTC (Tc * NSC)

__global__ __launch_bounds__(256, 2)
void lstm_persist(const __half* __restrict__ xt,
                  const __half* __restrict__ WpT,
                  const float* __restrict__ pb,
                  const float* __restrict__ c0,
                  __half* __restrict__ hT,
                  __half* __restrict__ hlast,
                  const int* __restrict__ cap_len,
                  unsigned int* __restrict__ counter)
{
    extern __shared__ __align__(1024) char smem[];
    uint32_t sb = smem_u32(smem);
    int tid = threadIdx.x, wid = tid >> 5, lid = tid & 31;
    int g = lid >> 2, tig = lid & 3;
    int warpM = (wid & 1) * 64, warpN = (wid >> 1) * 32;
    int bx = blockIdx.x, bmT = blockIdx.y;
    int bn = bx * 128, bm = bmT * 128;
    int jg0 = bn >> 2;
    float*  pb_s = (float*)smem;
    int*    cl_s = (int*)(smem + 512);
    __half* hsm  = (__half*)(smem + HS_OFF);   // pitch 40 halves (80B)

    uint32_t rowA[4], xmA[4];
    uint32_t cbA = (lid >> 4) * 16;
#pragma unroll
    for (int rb = 0; rb < 4; rb++) {
        int row = warpM + rb * 16 + (lid & 15);
        rowA[rb] = row * 128;
        xmA[rb]  = (row & 7) * 16;
    }
    uint32_t rowB[2], xmB[2];
    uint32_t cbB = ((lid >> 3) & 1) * 16;
#pragma unroll
    for (int p = 0; p < 2; p++) {
        int row = warpN + p * 16 + ((lid >> 4) << 3) + (lid & 7);
        rowB[p] = row * 128;
        xmB[p]  = (row & 7) * 16;
    }

    bool ev = (tig & 1) == 0;
    int Jl_base = (warpN >> 2) + (tig >> 1);
    float c_reg[4][4];
#pragma unroll
    for (int rb = 0; rb < 4; rb++) {
        int rrow = warpM + rb * 16 + g + (ev ? 0 : 8);
#pragma unroll
        for (int nb = 0; nb < 4; nb++) {
            int Jl = Jl_base + 2 * nb;
            c_reg[rb][nb] = c0[(size_t)(bm + rrow) * Hc + jg0 + Jl];
        }
    }
    if (tid < 128) {
        cl_s[tid] = cap_len[bm + tid];
        pb_s[tid] = pb[bn + tid];
    }
    if (tid == 0) {
#pragma unroll
        for (int i = 0; i < 3; i++) MBARRIER_INIT(sb + MB_OFF + i * 8, 1);
    }
    __syncthreads();

    int tsc = bx >> 1;
    int hoff = (bx & 1) * 32;

    auto load_gc = [&](int gc) {
        int t2 = gc / NSC, sc2 = gc % NSC;
        int s = gc % 3;
        uint32_t mb = sb + MB_OFF + s * 8;
        MBARRIER_EXPECT_TX(mb, STG);
        const char* asrc = (sc2 < 8)
            ? (const char*)xt + ((((size_t)t2 * 8 + bmT) * 8 + sc2) << 14)
            : (const char*)hT + ((((size_t)(t2 & 1) * 8 + bmT) * 16 + (sc2 - 8)) << 14);
        TMA_BULK(sb + SA_OFF + s * STG, asrc, 16384, mb);
        const char* bsrc = (const char*)WpT + (((size_t)bx * 24 + sc2) << 14);
        TMA_BULK(sb + SA_OFF + s * STG + 16384, bsrc, 16384, mb);
    };

    if (tid == 0) { load_gc(0); load_gc(1); }

    for (int t = 0; t < Tc; t++) {
        float acc[4][4][4];
#pragma unroll
        for (int i = 0; i < 4; i++)
#pragma unroll
            for (int j = 0; j < 4; j++)
#pragma unroll
                for (int q = 0; q < 4; q++) acc[i][j][q] = 0.f;

        for (int sc = 0; sc < NSC; sc++) {
            int gc = t * NSC + sc;
            if (sc == 6 && tid == 0) {
                unsigned int target = (unsigned int)(NCTA * t);
                unsigned int v;
                do {
                    asm volatile("ld.acquire.gpu.global.u32 %0, [%1];"
                                 : "=r"(v) : "l"(counter) : "memory");
                } while (v < target);
                FENCE_ASYNC();
            }
            MBARRIER_WAIT_PARITY(sb + MB_OFF + (gc % 3) * 8, (sc / 3) & 1);
            __syncthreads();
            if (tid == 0 && gc + 2 < TOTC) load_gc(gc + 2);
            uint32_t aB = sb + SA_OFF + (gc % 3) * STG;
            uint32_t bB = aB + 16384;
#pragma unroll
            for (int k16 = 0; k16 < 4; k16++) {
                uint32_t afr[4][4], bfr[2][4];
#pragma unroll
                for (int rb = 0; rb < 4; rb++)
                    ldsm_x4(afr[rb], aB + rowA[rb] + ((cbA + k16 * 32) ^ xmA[rb]));
#pragma unroll
                for (int p = 0; p < 2; p++)
                    ldsm_x4(bfr[p], bB + rowB[p] + ((cbB + k16 * 32) ^ xmB[p]));
#pragma unroll
                for (int rb = 0; rb < 4; rb++) {
                    mma_f16(acc[rb][0], afr[rb], &bfr[0][0]);
                    mma_f16(acc[rb][1], afr[rb], &bfr[0][2]);
                    mma_f16(acc[rb][2], afr[rb], &bfr[1][0]);
                    mma_f16(acc[rb][3], afr[rb], &bfr[1][2]);
                }
            }
        }

        // epilogue: shuffle gates -> hsm staging
#pragma unroll
        for (int rb = 0; rb < 4; rb++) {
            int r0 = warpM + rb * 16 + g;
            int rrow = ev ? r0 : (r0 + 8);
#pragma unroll
            for (int nb = 0; nb < 4; nb++) {
                float v0 = acc[rb][nb][0], v1 = acc[rb][nb][1];
                float v2 = acc[rb][nb][2], v3 = acc[rb][nb][3];
                float x = ev ? v2 : v0, y = ev ? v3 : v1;
                float px = __shfl_xor_sync(0xffffffffu, x, 1);
                float py = __shfl_xor_sync(0xffffffffu, y, 1);
                float gi = ev ? v0 : px, gf = ev ? v1 : py;
                float gg = ev ? px : v2, go = ev ? py : v3;
                int Jl = Jl_base + 2 * nb;
                float4 pbv = *(const float4*)(pb_s + 4 * Jl);
                float si = fsig(gi + pbv.x);
                float sf = fsig(gf + pbv.y);
                float tg = ftanh(gg + pbv.z);
                float so = fsig(go + pbv.w);
                float cn = sf * c_reg[rb][nb] + si * tg;
                c_reg[rb][nb] = cn;
                hsm[rrow * 40 + Jl] = __float2half_rn(so * ftanh(cn));
            }
        }
        __syncthreads();
        {
            char* tb = (char*)hT + ((((size_t)((t + 1) & 1) * 8 + bmT) * 16 + tsc) << 14);
            for (int idx = tid; idx < 512; idx += 256) {
                int row = idx >> 2, ch = idx & 3;
                int jl0 = ch * 8;
                float4 val = *(const float4*)(hsm + row * 40 + jl0);
                uint32_t off = row * 128 + (hoff + jl0) * 2;
                off ^= (off >> 3) & 0x70;
                *(float4*)(tb + off) = val;
                if (cl_s[row] - 1 == t)
                    *(float4*)(hlast + (size_t)(bm + row) * Hc + jg0 + jl0) = val;
            }
        }
        __syncthreads();
        if (tid == 0) {
            FENCE_ASYNC();
            asm volatile("red.release.gpu.global.add.u32 [%0], %1;"
                         :: "l"(counter), "r"(1u) : "memory");
        }
    }
}

// ---------------- launch ----------------
extern "C" void kernel_launch(void* const* d_in, const int* in_sizes, int n_in,
                              void* d_out, int out_size) {
    const int*   cap     = (const int*)  d_in[0];
    const int*   cap_len = (const int*)  d_in[1];
    const float* feat    = (const float*)d_in[2];
    const float* embed   = (const float*)d_in[3];
    const float* W_ih    = (const float*)d_in[4];
    const float* W_hh    = (const float*)d_in[5];
    const float* b_ih    = (const float*)d_in[6];
    const float* b_hh    = (const float*)d_in[7];
    const float* v_ih0   = (const float*)d_in[8];
    const float* g_ih0   = (const float*)d_in[9];
    const float* b_ih0   = (const float*)d_in[10];
    const float* v_ic0   = (const float*)d_in[11];
    const float* g_ic0   = (const float*)d_in[12];
    const float* b_ic0   = (const float*)d_in[13];
    const float* v_mu    = (const float*)d_in[14];
    const float* g_mu    = (const float*)d_in[15];
    const float* b_mu    = (const float*)d_in[16];
    const float* v_s2    = (const float*)d_in[17];
    const float* g_s2    = (const float*)d_in[18];
    const float* b_s2    = (const float*)d_in[19];
    float* out = (float*)d_out;

    __half *Wcat, *Wocat, *WpT, *xt, *hT, *h0, *hl, *ftH;
    float *bcat, *bocat, *pb, *c0;
    unsigned int* counter;
    cudaGetSymbolAddress((void**)&Wcat,    g_Wcat);
    cudaGetSymbolAddress((void**)&bcat,    g_bcat);
    cudaGetSymbolAddress((void**)&Wocat,   g_Wocat);
    cudaGetSymbolAddress((void**)&bocat,   g_bocat);
    cudaGetSymbolAddress((void**)&WpT,     g_WpT);
    cudaGetSymbolAddress((void**)&pb,      g_pb);
    cudaGetSymbolAddress((void**)&xt,      g_xt);
    cudaGetSymbolAddress((void**)&hT,      g_hT);
    cudaGetSymbolAddress((void**)&h0,      g_h0);
    cudaGetSymbolAddress((void**)&c0,      g_c0);
    cudaGetSymbolAddress((void**)&hl,      g_hl);
    cudaGetSymbolAddress((void**)&ftH,     g_ftH);
    cudaGetSymbolAddress((void**)&counter, g_counter);

    cudaFuncSetAttribute(hgemm,        cudaFuncAttributeMaxDynamicSharedMemorySize, SMEM_G);
    cudaFuncSetAttribute(lstm_persist, cudaFuncAttributeMaxDynamicSharedMemorySize, SMEM_P);

    cudaMemsetAsync(counter, 0, sizeof(unsigned int));

    // prep (fused): weight norm x4 -> one launch; bias packs -> one launch
    wn_all<<<2 * Hc + 2 * Lc, 256>>>(v_ih0, g_ih0, v_ic0, g_ic0, v_mu, g_mu, v_s2, g_s2,
                                     Wcat, Wocat);
    pack_bias<<<(2 * Hc + 2 * Lc + 255) / 256, 256>>>(b_ih0, b_ic0, b_mu, b_s2, bcat, bocat);
    permute_tiled<<<Nw, 128>>>(W_hh, W_ih, b_ih, b_hh, WpT, pb);
    half_copy<<<(Bc * Ac + 255) / 256, 256>>>(feat, ftH, Bc * Ac);

    // gather all embed tiles directly from fp32 table (no embH pass)
    gather_xt<<<(Tc * Bc) / 4, 256>>>(embed, cap, xt);

    // init: h0 (fp16 linear) and c0 (fp32), fused N=2048; repack h0 -> hT[0]
    {
        dim3 grid(2 * Hc / 128, Bc / 128);
        hgemm<<<grid, 256, SMEM_G>>>(ftH, Ac, Ac / 32, Wcat, Ac, bcat,
                                     (float*)h0, Hc, 1, c0, Hc, 0, Hc);
        repack_h0<<<(Bc * Hc / 8) / 256, 256>>>(h0, hT);
    }

    // recurrence: persistent kernel, all-TMA, continuous pipeline (R16-identical)
    {
        dim3 grid(Nw / 128, Bc / 128);       // (32, 8) = 256 CTAs, 2/SM
        lstm_persist<<<grid, 256, SMEM_P>>>(xt, WpT, pb, c0, hT, hl, cap_len, counter);
    }

    // outputs: mu and sigma2 fused, N=512
    {
        dim3 grid(2 * Lc / 128, Bc / 128);
        hgemm<<<grid, 256, SMEM_G>>>(hl, Hc, Hc / 32, Wocat, Hc, bocat,
                                     out, Lc, 0, out + Bc * Lc, Lc, 0, Lc);
    }
}